// round 8
// baseline (speedup 1.0000x reference)
#include <cuda_runtime.h>
#include <cuda_bf16.h>
#include <math.h>
#include <stdint.h>

#define BB 16
#define TT 800
#define EE 512
#define DD 1024
#define AA 512
#define OO 5000
#define LL 97
#define SOSEOS 4999
#define NBLK 148
#define NTH 512
#define NCH 9            // t-chunks per batch row in P1

// x staging strides (bf16 elems, +8 pad)
#define XS0 2568   // K0=2560
#define XS1 2056   // K1=2048
#define XSD 1032   // Kd=1024
#define RED_OFF 83968
#define SMEM_BYTES 92160

// ---------------- scratch ----------------
__device__ __align__(16) unsigned short g_preenc_bf[BB * TT * AA];
__device__ __align__(16) unsigned short g_hs_bf[BB * TT * EE];
__device__ __align__(16) unsigned short g_W0F[4096 * 2560];
__device__ __align__(16) unsigned short g_W1F[4096 * 2048];
__device__ __align__(16) unsigned short g_WdF[512 * 1024];
__device__ __align__(16) unsigned short g_eys_bf[BB * LL * DD];
__device__ __align__(16) unsigned short g_z0bf[BB * DD], g_z1bf[BB * DD];
__device__ __align__(16) unsigned short g_x1bf[BB * 2048];
__device__ __align__(16) unsigned short g_pctx[BB * NCH * AA];  // partial contexts
__device__ float g_pm[BB * NCH], g_ps[BB * NCH];
__device__ float g_b0[4096], g_b1[4096];
__device__ float g_c0[BB * DD], g_c1[BB * DD];
__device__ float g_dp[BB * AA];
__device__ float g_zall[BB * LL * DD];
__device__ float g_logits[(size_t)BB * LL * OO];
__device__ float g_nll[BB * LL];
__device__ volatile unsigned g_flag[NBLK];

// ---------------- helpers ----------------
__device__ __forceinline__ float tanh_ap(float x) {
    float y; asm("tanh.approx.f32 %0, %1;" : "=f"(y) : "f"(x)); return y;
}
__device__ __forceinline__ float sigm(float x) { return 1.0f / (1.0f + __expf(-x)); }
__device__ __forceinline__ unsigned short f2bf(float v) {
    return __bfloat16_as_ushort(__float2bfloat16_rn(v));
}
__device__ __forceinline__ unsigned pk2bf(float a, float b) {
    return (unsigned)f2bf(a) | ((unsigned)f2bf(b) << 16);
}
__device__ __forceinline__ void unp8(uint4 w, float* f) {
    f[0] = __uint_as_float(w.x << 16); f[1] = __uint_as_float(w.x & 0xffff0000u);
    f[2] = __uint_as_float(w.y << 16); f[3] = __uint_as_float(w.y & 0xffff0000u);
    f[4] = __uint_as_float(w.z << 16); f[5] = __uint_as_float(w.z & 0xffff0000u);
    f[6] = __uint_as_float(w.w << 16); f[7] = __uint_as_float(w.w & 0xffff0000u);
}

// one-hop all-to-all device barrier (148 co-resident blocks)
__device__ __forceinline__ void gbar(unsigned ep) {
    __syncthreads();
    if (threadIdx.x == 0) { __threadfence(); g_flag[blockIdx.x] = ep; }
    if (threadIdx.x < NBLK) { while (g_flag[threadIdx.x] < ep) { } }
    __syncthreads();
    if (threadIdx.x == 0) { __threadfence(); }   // SM-wide L1 invalidate + acquire
    __syncthreads();
}

// ---------------- prolog: pack weights into mma B-fragment layout ----------------
__global__ void pack_frag(const float* __restrict__ Wa, const float* __restrict__ Wb,
                          int Ka, int K, int N, unsigned short* __restrict__ dst) {
    int idx = blockIdx.x * 256 + threadIdx.x;
    if (idx >= N * K) return;
    int j = idx / K, k = idx - j * K;
    float v = (k < Ka) ? Wa[(size_t)j * Ka + k] : Wb[(size_t)j * (K - Ka) + (k - Ka)];
    int jt = j >> 3, n = j & 7, kt = k >> 4, kk = k & 15;
    int lane = n * 4 + ((kk & 7) >> 1);
    int comp = ((kt & 1) << 1) + (kk >> 3);
    size_t base = ((size_t)jt * (K >> 5) + (kt >> 1)) * 32 + lane;
    dst[base * 8 + comp * 2 + (kk & 1)] = f2bf(v);
}

// merged small prolog: pack_wd + convert_hs + prep state + embed gather + flags
__global__ void prep_all(const float* __restrict__ hs,
                         const float* __restrict__ Wdec,
                         const float* __restrict__ bih0, const float* __restrict__ bhh0,
                         const float* __restrict__ bih1, const float* __restrict__ bhh1,
                         const int* __restrict__ ys_pad, const float* __restrict__ embed,
                         unsigned short* __restrict__ wdf) {
    int idx = blockIdx.x * 256 + threadIdx.x;
    if (idx < BB * TT * EE) g_hs_bf[idx] = f2bf(hs[idx]);
    if (idx < 512 * 1024) {
        int j = idx / 1024, k = idx % 1024;
        int jt = j >> 3, n = j & 7, kt = k >> 4, kk = k & 15;
        int lane = n * 4 + ((kk & 7) >> 1);
        int comp = ((kt & 1) << 1) + (kk >> 3);
        size_t base = ((size_t)jt * 32 + (kt >> 1)) * 32 + lane;
        wdf[base * 8 + comp * 2 + (kk & 1)] = f2bf(Wdec[(size_t)j * 1024 + k]);
    }
    if (idx < 4096) {
        g_b0[idx] = bih0[idx] + bhh0[idx];
        g_b1[idx] = bih1[idx] + bhh1[idx];
    }
    if (idx < BB * DD) {
        g_c0[idx] = 0.f; g_c1[idx] = 0.f;
        g_z0bf[idx] = 0; g_z1bf[idx] = 0;
    }
    if (idx < BB * AA) g_dp[idx] = 0.f;
    if (idx < NBLK) g_flag[idx] = 0u;
    if (idx < BB * LL * DD) {
        int m = idx >> 10, d = idx & 1023;
        int b = m / LL, l = m % LL;
        int tok = (l == 0) ? SOSEOS : ys_pad[b * 96 + l - 1];
        g_eys_bf[idx] = f2bf(embed[(size_t)tok * DD + d]);
    }
}

// ---------------- generic NT GEMM (pre_enc + logits) ----------------
template <int STORE_BF>
__global__ __launch_bounds__(256) void gemm_nt(const float* __restrict__ A,
                                               const float* __restrict__ Bm,
                                               const float* __restrict__ bias,
                                               float* __restrict__ C,
                                               unsigned short* __restrict__ Cbf,
                                               int M, int N, int K) {
    __shared__ float As[8][128];
    __shared__ float Bs[8][128];
    int tid = threadIdx.x;
    int m0 = blockIdx.y * 128, n0 = blockIdx.x * 128;
    int lr = tid >> 1, lk = (tid & 1) * 4;
    int tx = tid & 15, ty = tid >> 4;
    float acc[8][8];
#pragma unroll
    for (int i = 0; i < 8; i++)
#pragma unroll
        for (int j = 0; j < 8; j++) acc[i][j] = 0.f;
    for (int k0 = 0; k0 < K; k0 += 8) {
        float4 av = make_float4(0.f,0.f,0.f,0.f), bv = make_float4(0.f,0.f,0.f,0.f);
        if (m0 + lr < M) av = *(const float4*)&A[(size_t)(m0 + lr) * K + k0 + lk];
        if (n0 + lr < N) bv = *(const float4*)&Bm[(size_t)(n0 + lr) * K + k0 + lk];
        __syncthreads();
        As[lk+0][lr]=av.x; As[lk+1][lr]=av.y; As[lk+2][lr]=av.z; As[lk+3][lr]=av.w;
        Bs[lk+0][lr]=bv.x; Bs[lk+1][lr]=bv.y; Bs[lk+2][lr]=bv.z; Bs[lk+3][lr]=bv.w;
        __syncthreads();
#pragma unroll
        for (int kk = 0; kk < 8; kk++) {
            float a[8], b[8];
            *(float4*)(a)   = *(const float4*)&As[kk][ty*8];
            *(float4*)(a+4) = *(const float4*)&As[kk][ty*8+4];
            *(float4*)(b)   = *(const float4*)&Bs[kk][tx*8];
            *(float4*)(b+4) = *(const float4*)&Bs[kk][tx*8+4];
#pragma unroll
            for (int i = 0; i < 8; i++)
#pragma unroll
                for (int j = 0; j < 8; j++) acc[i][j] += a[i] * b[j];
        }
    }
#pragma unroll
    for (int i = 0; i < 8; i++) {
        int m = m0 + ty*8 + i;
        if (m >= M) continue;
#pragma unroll
        for (int j = 0; j < 8; j++) {
            int n = n0 + tx*8 + j;
            if (n < N) {
                float v = acc[i][j] + bias[n];
                if (STORE_BF) Cbf[(size_t)m * N + n] = f2bf(v);
                else          C[(size_t)m * N + n] = v;
            }
        }
    }
}

// ---------------- warp-level mma over one n8 tile, k-slice ----------------
__device__ __forceinline__ void warp_mma(const uint4* __restrict__ wf, int KT32, int jt,
                                         int ktp0, int nktp, const unsigned short* xs,
                                         int XSTR, int lane, float* c) {
    int m = lane >> 3, r = lane & 7;
    int row = r + ((m & 1) << 3);
    int colh = m >> 1;
    unsigned sbase = (unsigned)__cvta_generic_to_shared(xs) + (unsigned)((row * XSTR + colh * 8) * 2);
    const uint4* wp = wf + (size_t)jt * KT32 * 32 + lane;
#pragma unroll 4
    for (int t = 0; t < nktp; t++) {
        int ktp = ktp0 + t;
        unsigned a0,a1,a2,a3, e0,e1,e2,e3;
        unsigned addr0 = sbase + (unsigned)(ktp * 64);
        asm volatile("ldmatrix.sync.aligned.m8n8.x4.shared.b16 {%0,%1,%2,%3}, [%4];"
            : "=r"(a0),"=r"(a1),"=r"(a2),"=r"(a3) : "r"(addr0));
        asm volatile("ldmatrix.sync.aligned.m8n8.x4.shared.b16 {%0,%1,%2,%3}, [%4];"
            : "=r"(e0),"=r"(e1),"=r"(e2),"=r"(e3) : "r"(addr0 + 32u));
        uint4 wv = wp[(size_t)ktp * 32];
        asm volatile("mma.sync.aligned.m16n8k16.row.col.f32.bf16.bf16.f32 "
            "{%0,%1,%2,%3}, {%4,%5,%6,%7}, {%8,%9}, {%0,%1,%2,%3};"
            : "+f"(c[0]),"+f"(c[1]),"+f"(c[2]),"+f"(c[3])
            : "r"(a0),"r"(a1),"r"(a2),"r"(a3), "r"(wv.x),"r"(wv.y));
        asm volatile("mma.sync.aligned.m16n8k16.row.col.f32.bf16.bf16.f32 "
            "{%0,%1,%2,%3}, {%4,%5,%6,%7}, {%8,%9}, {%0,%1,%2,%3};"
            : "+f"(c[0]),"+f"(c[1]),"+f"(c[2]),"+f"(c[3])
            : "r"(e0),"r"(e1),"r"(e2),"r"(e3), "r"(wv.z),"r"(wv.w));
    }
}

// ---------------- persistent decoder loop ----------------
extern "C" __global__ void __launch_bounds__(NTH, 1)
decoder_loop(const int* __restrict__ hlens, const float* __restrict__ gvec) {
    extern __shared__ __align__(16) char smem[];
    __shared__ float s_red[16];
    __shared__ float s_bc[2];
    __shared__ float s_scale[BB][NCH];
    const int bid = blockIdx.x, tid = threadIdx.x;
    const int lane = tid & 31, wid = tid >> 5;
    unsigned ep = 0;

    for (int l = 0; l < LL; l++) {
        // ===== P1: chunk scores + partial softmax context (144 blocks: b x 9 chunks) =====
        if (bid < BB * NCH) {
            int b = bid & 15, c = bid >> 4;
            int t0 = c * 89;
            int tn = min(89, TT - t0);
            int hlen = hlens[b];
            float* dp   = (float*)smem;          // 512
            float* gv   = dp + 512;              // 512
            float* se   = gv + 512;              // 96
            float* ctxs = se + 96;               // 16*512
            float* ssum = ctxs + 8192;           // 16
            for (int a = tid; a < 512; a += NTH) {
                dp[a] = g_dp[b * 512 + a];
                gv[a] = gvec[a];
            }
            __syncthreads();
            // pass A: raw scores for this chunk
            for (int tt = wid; tt < tn; tt += 16) {
                int t = t0 + tt;
                const unsigned* pe = (const unsigned*)g_preenc_bf + ((size_t)b * TT + t) * 256;
                float acc = 0.f;
#pragma unroll
                for (int p = 0; p < 8; p++) {
                    int q = lane + 32 * p;
                    unsigned v = pe[q];
                    float lo = __uint_as_float(v << 16);
                    float hi = __uint_as_float(v & 0xffff0000u);
                    float2 d2 = *(const float2*)&dp[2 * q];
                    float2 g2 = *(const float2*)&gv[2 * q];
                    acc += g2.x * tanh_ap(lo + d2.x);
                    acc += g2.y * tanh_ap(hi + d2.y);
                }
#pragma unroll
                for (int o = 16; o; o >>= 1) acc += __shfl_xor_sync(~0u, acc, o);
                if (lane == 0) se[tt] = (t < hlen) ? acc : -1e30f;
            }
            __syncthreads();
            // chunk max
            float mx = (tid < tn) ? se[tid] : -1e30f;
#pragma unroll
            for (int o = 16; o; o >>= 1) mx = fmaxf(mx, __shfl_xor_sync(~0u, mx, o));
            if (lane == 0) s_red[wid] = mx;
            __syncthreads();
            if (tid == 0) { float m = s_red[0]; for (int i = 1; i < 16; i++) m = fmaxf(m, s_red[i]); s_bc[0] = m; }
            __syncthreads();
            float m = s_bc[0];
            // pass B: weighted partial context
            float ctx[16];
#pragma unroll
            for (int i = 0; i < 16; i++) ctx[i] = 0.f;
            float ws = 0.f;
            const unsigned* hb = (const unsigned*)g_hs_bf + (size_t)b * TT * 256;
            for (int tt = wid; tt < tn; tt += 16) {
                int t = t0 + tt;
                float w = __expf(2.0f * (se[tt] - m));
                if (t >= hlen) w = 0.f;
                ws += w;
                const unsigned* hp = hb + (size_t)t * 256;
#pragma unroll
                for (int p = 0; p < 8; p++) {
                    unsigned v = hp[p * 32 + lane];
                    ctx[2 * p]     = fmaf(w, __uint_as_float(v << 16), ctx[2 * p]);
                    ctx[2 * p + 1] = fmaf(w, __uint_as_float(v & 0xffff0000u), ctx[2 * p + 1]);
                }
            }
#pragma unroll
            for (int p = 0; p < 8; p++)
                *(float2*)&ctxs[wid * 512 + 2 * (p * 32 + lane)] = make_float2(ctx[2 * p], ctx[2 * p + 1]);
            if (lane == 0) ssum[wid] = ws;
            __syncthreads();
            {
                float s = 0.f;
#pragma unroll
                for (int y = 0; y < 16; y++) s += ctxs[y * 512 + tid];
                g_pctx[((b * NCH + c) << 9) + tid] = f2bf(s);
            }
            if (tid == 0) {
                float S = 0.f;
#pragma unroll
                for (int i = 0; i < 16; i++) S += ssum[i];
                g_pm[b * NCH + c] = m;
                g_ps[b * NCH + c] = S;
            }
        }
        gbar(++ep);

        // ===== P2: gates0 + cell0 (128 blocks; ctx combine folded into staging) =====
        if (bid < 128) {
            unsigned short* xs = (unsigned short*)smem;
            float* red = (float*)(smem + RED_OFF);
            if (tid < 16) {
                int b = tid;
                float M = -1e30f;
#pragma unroll
                for (int j = 0; j < NCH; j++) M = fmaxf(M, g_pm[b * NCH + j]);
                float S = 0.f;
                float sc[NCH];
#pragma unroll
                for (int j = 0; j < NCH; j++) {
                    sc[j] = __expf(2.0f * (g_pm[b * NCH + j] - M));
                    S += g_ps[b * NCH + j] * sc[j];
                }
                float inv = 1.0f / S;
#pragma unroll
                for (int j = 0; j < NCH; j++) s_scale[b][j] = sc[j] * inv;
            }
            __syncthreads();
            uint4* xd = (uint4*)xs;
            for (int i = tid; i < 5120; i += NTH) {
                int b = i / 320, q = i - b * 320;
                uint4 v;
                if (q < 128) {
                    v = ((const uint4*)g_eys_bf)[(size_t)(b * LL + l) * 128 + q];
                } else if (q < 192) {
                    float o[8];
#pragma unroll
                    for (int r = 0; r < 8; r++) o[r] = 0.f;
#pragma unroll
                    for (int j = 0; j < NCH; j++) {
                        float sc = s_scale[b][j];
                        uint4 pv = ((const uint4*)g_pctx)[((b * NCH + j) << 6) + (q - 128)];
                        float pf[8]; unp8(pv, pf);
#pragma unroll
                        for (int r = 0; r < 8; r++) o[r] = fmaf(sc, pf[r], o[r]);
                    }
                    v.x = pk2bf(o[0], o[1]); v.y = pk2bf(o[2], o[3]);
                    v.z = pk2bf(o[4], o[5]); v.w = pk2bf(o[6], o[7]);
                } else {
                    v = ((const uint4*)g_z0bf)[b * 128 + (q - 192)];
                }
                xd[b * 321 + q] = v;
            }
            __syncthreads();
            int g = wid & 3, ks = wid >> 2;
            float c[4] = {0.f, 0.f, 0.f, 0.f};
            warp_mma((const uint4*)g_W0F, 80, g * 128 + bid, ks * 20, 20, xs, XS0, lane, c);
            float* rw = &red[(wid * 32 + lane) * 4];
            rw[0] = c[0]; rw[1] = c[1]; rw[2] = c[2]; rw[3] = c[3];
            __syncthreads();
            if (tid < 128) {
                int b = tid >> 3, dl = tid & 7, d = bid * 8 + dl;
                int lr = (b & 7) * 4 + (dl >> 1);
                int rg = ((b >> 3) << 1) + (dl & 1);
                float gv4[4];
#pragma unroll
                for (int gg = 0; gg < 4; gg++) {
                    float s = 0.f;
#pragma unroll
                    for (int k2 = 0; k2 < 4; k2++) s += red[((k2 * 4 + gg) * 32 + lr) * 4 + rg];
                    gv4[gg] = s;
                }
                float gi = gv4[0] + g_b0[d], gf = gv4[1] + g_b0[1024 + d];
                float gg = gv4[2] + g_b0[2048 + d], go = gv4[3] + g_b0[3072 + d];
                int u = b * 1024 + d;
                float cc = sigm(gf) * g_c0[u] + sigm(gi) * tanh_ap(gg);
                float h = sigm(go) * tanh_ap(cc);
                g_c0[u] = cc;
                unsigned short hb = f2bf(h);
                g_z0bf[u] = hb;
                g_x1bf[b * 2048 + d] = hb;
                g_x1bf[b * 2048 + 1024 + d] = g_z1bf[u];
            }
        }
        gbar(++ep);

        // ===== P3: gates1 + cell1 (128 blocks) | dec_proj next step (16 blocks) =====
        if (bid < 128) {
            unsigned short* xs = (unsigned short*)smem;
            float* red = (float*)(smem + RED_OFF);
            uint4* xd = (uint4*)xs;
            for (int i = tid; i < 4096; i += NTH) {
                int b = i >> 8, q = i & 255;
                xd[b * 257 + q] = ((const uint4*)g_x1bf)[b * 256 + q];
            }
            __syncthreads();
            int g = wid & 3, ks = wid >> 2;
            float c[4] = {0.f, 0.f, 0.f, 0.f};
            warp_mma((const uint4*)g_W1F, 64, g * 128 + bid, ks * 16, 16, xs, XS1, lane, c);
            float* rw = &red[(wid * 32 + lane) * 4];
            rw[0] = c[0]; rw[1] = c[1]; rw[2] = c[2]; rw[3] = c[3];
            __syncthreads();
            if (tid < 128) {
                int b = tid >> 3, dl = tid & 7, d = bid * 8 + dl;
                int lr = (b & 7) * 4 + (dl >> 1);
                int rg = ((b >> 3) << 1) + (dl & 1);
                float gv4[4];
#pragma unroll
                for (int gg = 0; gg < 4; gg++) {
                    float s = 0.f;
#pragma unroll
                    for (int k2 = 0; k2 < 4; k2++) s += red[((k2 * 4 + gg) * 32 + lr) * 4 + rg];
                    gv4[gg] = s;
                }
                float gi = gv4[0] + g_b1[d], gf = gv4[1] + g_b1[1024 + d];
                float gg = gv4[2] + g_b1[2048 + d], go = gv4[3] + g_b1[3072 + d];
                int u = b * 1024 + d;
                float cc = sigm(gf) * g_c1[u] + sigm(gi) * tanh_ap(gg);
                float h = sigm(go) * tanh_ap(cc);
                g_c1[u] = cc;
                g_z1bf[u] = f2bf(h);
                g_zall[((size_t)b * LL + l) * 1024 + d] = h;
            }
        } else if (bid < 144) {
            unsigned short* xs = (unsigned short*)smem;
            float* red = (float*)(smem + RED_OFF);
            uint4* xd = (uint4*)xs;
            for (int i = tid; i < 2048; i += NTH) {
                int b = i >> 7, q = i & 127;
                xd[b * 129 + q] = ((const uint4*)g_z0bf)[b * 128 + q];
            }
            __syncthreads();
            int ti = wid & 3, ks = wid >> 2;
            float c[4] = {0.f, 0.f, 0.f, 0.f};
            warp_mma((const uint4*)g_WdF, 32, (bid - 128) * 4 + ti, ks * 8, 8, xs, XSD, lane, c);
            float* rw = &red[(wid * 32 + lane) * 4];
            rw[0] = c[0]; rw[1] = c[1]; rw[2] = c[2]; rw[3] = c[3];
            __syncthreads();
            {
                int ti2 = tid >> 7, rem = tid & 127;
                int b = rem >> 3, al = rem & 7;
                int lr = (b & 7) * 4 + (al >> 1);
                int rg = ((b >> 3) << 1) + (al & 1);
                float s = 0.f;
#pragma unroll
                for (int k2 = 0; k2 < 4; k2++) s += red[((k2 * 4 + ti2) * 32 + lr) * 4 + rg];
                g_dp[b * 512 + (bid - 128) * 32 + ti2 * 8 + al] = s;
            }
        }
        gbar(++ep);
    }
}

// ---------------- epilogue: online single-pass logsumexp NLL ----------------
__global__ __launch_bounds__(256) void nll_kernel(const int* __restrict__ ys_pad) {
    __shared__ float redm[256], reds[256];
    int m = blockIdx.x, tid = threadIdx.x;
    int b = m / LL, l = m % LL;
    const float* row = &g_logits[(size_t)m * OO];
    float mx = -1e30f, s = 0.f;
    for (int i = tid; i < OO; i += 256) {
        float v = row[i];
        if (v > mx) { s = s * __expf(mx - v) + 1.0f; mx = v; }
        else s += __expf(v - mx);
    }
    redm[tid] = mx; reds[tid] = s;
    __syncthreads();
    for (int st = 128; st; st >>= 1) {
        if (tid < st) {
            float m2 = redm[tid + st], s2 = reds[tid + st];
            float M = fmaxf(redm[tid], m2);
            reds[tid] = reds[tid] * __expf(redm[tid] - M) + s2 * __expf(m2 - M);
            redm[tid] = M;
        }
        __syncthreads();
    }
    if (tid == 0) {
        int tgt = (l < 96) ? ys_pad[b * 96 + l] : SOSEOS;
        g_nll[m] = logf(reds[0]) + redm[0] - row[tgt];
    }
}
__global__ __launch_bounds__(256) void finalize(float* out) {
    __shared__ float red[256];
    int tid = threadIdx.x;
    float acc = 0.f;
    for (int i = tid; i < BB * LL; i += 256) acc += g_nll[i];
    red[tid] = acc; __syncthreads();
    for (int s = 128; s; s >>= 1) { if (tid < s) red[tid] += red[tid + s]; __syncthreads(); }
    if (tid == 0) out[0] = red[0] * (96.0f / (float)(BB * LL));
}

// ---------------- launch ----------------
extern "C" void kernel_launch(void* const* d_in, const int* in_sizes, int n_in,
                              void* d_out, int out_size) {
    const float* hs_pad = (const float*)d_in[0];
    const int*   hlens  = (const int*)d_in[1];
    const int*   ys_pad = (const int*)d_in[2];
    const float* embed  = (const float*)d_in[3];
    const float* W_ih0  = (const float*)d_in[4];
    const float* W_hh0  = (const float*)d_in[5];
    const float* b_ih0  = (const float*)d_in[6];
    const float* b_hh0  = (const float*)d_in[7];
    const float* W_ih1  = (const float*)d_in[8];
    const float* W_hh1  = (const float*)d_in[9];
    const float* b_ih1  = (const float*)d_in[10];
    const float* b_hh1  = (const float*)d_in[11];
    const float* W_enc  = (const float*)d_in[12];
    const float* b_enc  = (const float*)d_in[13];
    const float* W_dec  = (const float*)d_in[14];
    const float* gvec   = (const float*)d_in[15];
    const float* W_out  = (const float*)d_in[16];
    const float* b_out  = (const float*)d_in[17];
    float* out = (float*)d_out;

    unsigned short *d_w0f, *d_w1f, *d_wdf;
    cudaGetSymbolAddress((void**)&d_w0f, g_W0F);
    cudaGetSymbolAddress((void**)&d_w1f, g_W1F);
    cudaGetSymbolAddress((void**)&d_wdf, g_WdF);

    pack_frag<<<(4096 * 2560 + 255) / 256, 256>>>(W_ih0, W_hh0, 1536, 2560, 4096, d_w0f);
    pack_frag<<<(4096 * 2048 + 255) / 256, 256>>>(W_ih1, W_hh1, 1024, 2048, 4096, d_w1f);
    prep_all<<<(BB * TT * EE + 255) / 256, 256>>>(hs_pad, W_dec, b_ih0, b_hh0, b_ih1, b_hh1,
                                                  ys_pad, embed, d_wdf);

    // pre_enc = hs_pad @ W_enc^T + b_enc -> bf16
    gemm_nt<1><<<dim3(4, 100), 256>>>(hs_pad, W_enc, b_enc, nullptr, g_preenc_bf, BB * TT, AA, EE);

    // all 97 recurrent steps in one persistent kernel
    cudaFuncSetAttribute(decoder_loop, cudaFuncAttributeMaxDynamicSharedMemorySize, SMEM_BYTES);
    decoder_loop<<<NBLK, NTH, SMEM_BYTES>>>(hlens, gvec);

    // logits = z_all @ W_out^T + b_out
    gemm_nt<0><<<dim3(40, 13), 256>>>(g_zall, W_out, b_out, g_logits, nullptr, BB * LL, OO, DD);
    nll_kernel<<<BB * LL, 256>>>(ys_pad);
    finalize<<<1, 256>>>(out);
}

// round 9
// speedup vs baseline: 2.5249x; 2.5249x over previous
#include <cuda_runtime.h>
#include <cuda_bf16.h>
#include <math.h>
#include <stdint.h>

#define BB 16
#define TT 800
#define EE 512
#define DD 1024
#define AA 512
#define OO 5000
#define LL 97
#define SOSEOS 4999
#define NBLK 148
#define NTH 512

// x staging strides (bf16 elems, +8 pad)
#define XS0 2568   // K0=2560
#define XS1 2056   // K1=2048
#define XSD 1032   // Kd=1024
#define RED_OFF 83968
#define SMEM_BYTES 92160

// ---------------- scratch ----------------
__device__ __align__(16) unsigned short g_preenc_bf[BB * TT * AA];
__device__ __align__(16) unsigned short g_hs_bf[BB * TT * EE];
__device__ __align__(16) unsigned short g_W0F[4096 * 2560];   // mma B-fragment layouts
__device__ __align__(16) unsigned short g_W1F[4096 * 2048];
__device__ __align__(16) unsigned short g_WdF[512 * 1024];
__device__ __align__(16) unsigned short g_WeF[512 * 512];
__device__ __align__(16) unsigned short g_WoF[5000 * 1024];
__device__ __align__(16) unsigned short g_eys_bf[BB * LL * DD];
__device__ __align__(16) unsigned short g_z0bf[BB * DD], g_z1bf[BB * DD];
__device__ __align__(16) unsigned short g_attc_bf[BB * AA];
__device__ __align__(16) unsigned short g_x1bf[BB * 2048];
__device__ __align__(16) unsigned short g_zallbf[BB * LL * DD];
__device__ float g_b0[4096], g_b1[4096];
__device__ float g_c0[BB * DD], g_c1[BB * DD];
__device__ float g_dp[BB * AA];
__device__ float g_escore[BB * TT];
__device__ float g_logits[(size_t)BB * LL * OO];
__device__ float g_nll[BB * LL];
__device__ volatile unsigned g_arr[NBLK];
__device__ volatile unsigned g_rel;

// ---------------- helpers ----------------
__device__ __forceinline__ float tanh_ap(float x) {
    float y; asm("tanh.approx.f32 %0, %1;" : "=f"(y) : "f"(x)); return y;
}
__device__ __forceinline__ float sigm(float x) { return 1.0f / (1.0f + __expf(-x)); }
__device__ __forceinline__ unsigned short f2bf(float v) {
    return __bfloat16_as_ushort(__float2bfloat16_rn(v));
}

// device-wide barrier (148 co-resident blocks) — R6 proven version
__device__ __forceinline__ void gbar(unsigned ep) {
    __syncthreads();
    if (threadIdx.x == 0) {
        __threadfence();
        g_arr[blockIdx.x] = ep;
    }
    if (blockIdx.x == 0) {
        if (threadIdx.x < NBLK) {
            while (g_arr[threadIdx.x] < ep) { }
        }
        __syncthreads();
        if (threadIdx.x == 0) { __threadfence(); g_rel = ep; }
    }
    if (threadIdx.x == 0) {
        while (g_rel < ep) { }
        __threadfence();
    }
    __syncthreads();
}

// ---------------- prolog: pack weights into mma B-fragment layout ----------------
__global__ void pack_frag(const float* __restrict__ Wa, const float* __restrict__ Wb,
                          int Ka, int K, int N, unsigned short* __restrict__ dst) {
    int idx = blockIdx.x * 256 + threadIdx.x;
    if (idx >= N * K) return;
    int j = idx / K, k = idx - j * K;
    float v = (k < Ka) ? Wa[(size_t)j * Ka + k] : Wb[(size_t)j * (K - Ka) + (k - Ka)];
    int jt = j >> 3, n = j & 7, kt = k >> 4, kk = k & 15;
    int lane = n * 4 + ((kk & 7) >> 1);
    int comp = ((kt & 1) << 1) + (kk >> 3);
    size_t base = ((size_t)jt * (K >> 5) + (kt >> 1)) * 32 + lane;
    dst[base * 8 + comp * 2 + (kk & 1)] = f2bf(v);
}

// merged small prolog
__global__ void prep_all(const float* __restrict__ hs,
                         const float* __restrict__ Wdec,
                         const float* __restrict__ bih0, const float* __restrict__ bhh0,
                         const float* __restrict__ bih1, const float* __restrict__ bhh1,
                         const int* __restrict__ ys_pad, const float* __restrict__ embed,
                         unsigned short* __restrict__ wdf) {
    int idx = blockIdx.x * 256 + threadIdx.x;
    if (idx < BB * TT * EE) g_hs_bf[idx] = f2bf(hs[idx]);
    if (idx < 512 * 1024) {
        int j = idx / 1024, k = idx % 1024;
        int jt = j >> 3, n = j & 7, kt = k >> 4, kk = k & 15;
        int lane = n * 4 + ((kk & 7) >> 1);
        int comp = ((kt & 1) << 1) + (kk >> 3);
        size_t base = ((size_t)jt * 32 + (kt >> 1)) * 32 + lane;
        wdf[base * 8 + comp * 2 + (kk & 1)] = f2bf(Wdec[(size_t)j * 1024 + k]);
    }
    if (idx < 4096) {
        g_b0[idx] = bih0[idx] + bhh0[idx];
        g_b1[idx] = bih1[idx] + bhh1[idx];
    }
    if (idx < BB * DD) {
        g_c0[idx] = 0.f; g_c1[idx] = 0.f;
        g_z0bf[idx] = 0; g_z1bf[idx] = 0;
    }
    if (idx < BB * AA) g_dp[idx] = 0.f;
    if (idx < NBLK) g_arr[idx] = 0u;
    if (idx == 0) g_rel = 0u;
    if (idx < BB * LL * DD) {
        int m = idx >> 10, d = idx & 1023;
        int b = m / LL, l = m % LL;
        int tok = (l == 0) ? SOSEOS : ys_pad[b * 96 + l - 1];
        g_eys_bf[idx] = f2bf(embed[(size_t)tok * DD + d]);
    }
}

// ---------------- warp-level mma over one n8 tile, k-slice ----------------
__device__ __forceinline__ void warp_mma(const uint4* __restrict__ wf, int KT32, int jt,
                                         int ktp0, int nktp, const unsigned short* xs,
                                         int XSTR, int lane, float* c) {
    int m = lane >> 3, r = lane & 7;
    int row = r + ((m & 1) << 3);
    int colh = m >> 1;
    unsigned sbase = (unsigned)__cvta_generic_to_shared(xs) + (unsigned)((row * XSTR + colh * 8) * 2);
    const uint4* wp = wf + (size_t)jt * KT32 * 32 + lane;
#pragma unroll 4
    for (int t = 0; t < nktp; t++) {
        int ktp = ktp0 + t;
        unsigned a0,a1,a2,a3, e0,e1,e2,e3;
        unsigned addr0 = sbase + (unsigned)(ktp * 64);
        asm volatile("ldmatrix.sync.aligned.m8n8.x4.shared.b16 {%0,%1,%2,%3}, [%4];"
            : "=r"(a0),"=r"(a1),"=r"(a2),"=r"(a3) : "r"(addr0));
        asm volatile("ldmatrix.sync.aligned.m8n8.x4.shared.b16 {%0,%1,%2,%3}, [%4];"
            : "=r"(e0),"=r"(e1),"=r"(e2),"=r"(e3) : "r"(addr0 + 32u));
        uint4 wv = wp[(size_t)ktp * 32];
        asm volatile("mma.sync.aligned.m16n8k16.row.col.f32.bf16.bf16.f32 "
            "{%0,%1,%2,%3}, {%4,%5,%6,%7}, {%8,%9}, {%0,%1,%2,%3};"
            : "+f"(c[0]),"+f"(c[1]),"+f"(c[2]),"+f"(c[3])
            : "r"(a0),"r"(a1),"r"(a2),"r"(a3), "r"(wv.x),"r"(wv.y));
        asm volatile("mma.sync.aligned.m16n8k16.row.col.f32.bf16.bf16.f32 "
            "{%0,%1,%2,%3}, {%4,%5,%6,%7}, {%8,%9}, {%0,%1,%2,%3};"
            : "+f"(c[0]),"+f"(c[1]),"+f"(c[2]),"+f"(c[3])
            : "r"(e0),"r"(e1),"r"(e2),"r"(e3), "r"(wv.z),"r"(wv.w));
    }
}

// ---------------- tensor-core GEMM: C[M,N] = A[M,K](bf16) x Bfrag^T + bias ----------------
// 512 threads = 16 warps. MSL m16-slices per block; 16/MSL n8-tiles per block.
template <int MSL, int STORE_BF>
__global__ __launch_bounds__(512) void gemm_mma(const unsigned short* __restrict__ A,
        const uint4* __restrict__ BF, const float* __restrict__ bias,
        float* __restrict__ C, unsigned short* __restrict__ Cbf,
        int M, int N, int K) {
    extern __shared__ __align__(16) unsigned short xsd[];
    const int XSTR = K + 8;
    const int tid = threadIdx.x, lane = tid & 31, wid = tid >> 5;
    const int MT = MSL * 16, NTILE = 16 / MSL;
    int m0 = blockIdx.y * MT;
    int n0 = blockIdx.x * NTILE * 8;
    // stage A tile [MT x K]
    int kq = K >> 3;
    const uint4* Ag = (const uint4*)A;
    for (int i = tid; i < MT * kq; i += 512) {
        int r = i / kq, q = i - r * kq;
        ((uint4*)(xsd + r * XSTR))[q] = Ag[(size_t)(m0 + r) * kq + q];
    }
    __syncthreads();
    int mi = wid / NTILE, nj = wid % NTILE;
    int jt = (n0 >> 3) + nj;
    if (jt * 8 < N) {
        float c[4] = {0.f, 0.f, 0.f, 0.f};
        warp_mma(BF, K >> 5, jt, 0, K >> 5, xsd + mi * 16 * XSTR, XSTR, lane, c);
        int row0 = m0 + mi * 16;
#pragma unroll
        for (int r = 0; r < 4; r++) {
            int row = row0 + (lane >> 2) + 8 * (r >> 1);
            int col = jt * 8 + (lane & 3) * 2 + (r & 1);
            float v = c[r] + bias[col];
            if (STORE_BF) Cbf[(size_t)row * N + col] = f2bf(v);
            else          C[(size_t)row * N + col] = v;
        }
    }
}

// ---------------- persistent decoder loop (R6 structure) ----------------
extern "C" __global__ void __launch_bounds__(NTH, 1)
decoder_loop(const int* __restrict__ hlens, const float* __restrict__ gvec) {
    extern __shared__ __align__(16) char smem[];
    __shared__ float s_red[16];
    __shared__ float s_bc[2];
    const int bid = blockIdx.x, tid = threadIdx.x;
    const int lane = tid & 31, wid = tid >> 5;
    unsigned ep = 0;

    for (int l = 0; l < LL; l++) {
        // ===== P1: e[b,t] = sum_a gvec[a]*tanh(pre_enc + dp) =====
        {
            int r0 = bid * 86 + min(bid, 72);
            int nr = 86 + (bid < 72 ? 1 : 0);
            int b0 = r0 / 800;
            float* dp = (float*)smem;            // 1024
            float* gv = (float*)(smem + 4096);   // 512
            for (int a = tid; a < 512; a += NTH) {
                dp[a] = g_dp[b0 * 512 + a];
                dp[512 + a] = (b0 + 1 < 16) ? g_dp[(b0 + 1) * 512 + a] : 0.f;
                gv[a] = gvec[a];
            }
            __syncthreads();
            for (int r = r0 + wid; r < r0 + nr; r += 16) {
                int b = r / 800;
                const unsigned* pe = (const unsigned*)g_preenc_bf + (size_t)r * 256;
                const float* dpb = dp + (b - b0) * 512;
                float acc = 0.f;
#pragma unroll
                for (int p = 0; p < 8; p++) {
                    int q = lane + 32 * p;
                    unsigned v = pe[q];
                    float lo = __uint_as_float(v << 16);
                    float hi = __uint_as_float(v & 0xffff0000u);
                    float2 d2 = *(const float2*)&dpb[2 * q];
                    float2 g2 = *(const float2*)&gv[2 * q];
                    acc += g2.x * tanh_ap(lo + d2.x);
                    acc += g2.y * tanh_ap(hi + d2.y);
                }
#pragma unroll
                for (int o = 16; o; o >>= 1) acc += __shfl_xor_sync(~0u, acc, o);
                if (lane == 0) g_escore[r] = acc;
            }
        }
        gbar(++ep);

        // ===== P2: softmax + att_c (bf16) =====
        if (bid < 128) {
            int b = bid >> 3, ec = bid & 7;
            int hlen = hlens[b];
            float* s_w  = (float*)smem;            // 800
            float* s_at = (float*)(smem + 4096);   // 1024
            const float* e = &g_escore[b * 800];
            float mx = -1e30f;
            for (int t = tid; t < 800; t += NTH)
                if (t < hlen) mx = fmaxf(mx, e[t]);
#pragma unroll
            for (int o = 16; o; o >>= 1) mx = fmaxf(mx, __shfl_xor_sync(~0u, mx, o));
            if (lane == 0) s_red[wid] = mx;
            __syncthreads();
            if (tid == 0) { float m = s_red[0]; for (int i = 1; i < 16; i++) m = fmaxf(m, s_red[i]); s_bc[0] = m; }
            __syncthreads();
            mx = s_bc[0];
            float sum = 0.f;
            for (int t = tid; t < 800; t += NTH) {
                float w = (t < hlen) ? __expf(2.0f * (e[t] - mx)) : 0.f;
                s_w[t] = w;
                sum += w;
            }
#pragma unroll
            for (int o = 16; o; o >>= 1) sum += __shfl_xor_sync(~0u, sum, o);
            if (lane == 0) s_red[wid] = sum;
            __syncthreads();
            if (tid == 0) { float s = 0.f; for (int i = 0; i < 16; i++) s += s_red[i]; s_bc[1] = 1.0f / s; }
            __syncthreads();
            float inv = s_bc[1];
            for (int t = tid; t < 800; t += NTH) s_w[t] *= inv;
            __syncthreads();
            {
                const unsigned* hp = (const unsigned*)g_hs_bf + (size_t)b * 800 * 256 + ec * 32 + lane;
                float a0 = 0.f, a1 = 0.f;
#pragma unroll 5
                for (int t = wid; t < 800; t += 16) {
                    unsigned v = hp[(size_t)t * 256];
                    float w = s_w[t];
                    a0 = fmaf(w, __uint_as_float(v << 16), a0);
                    a1 = fmaf(w, __uint_as_float(v & 0xffff0000u), a1);
                }
                *(float2*)&s_at[wid * 64 + lane * 2] = make_float2(a0, a1);
            }
            __syncthreads();
            if (tid < 64) {
                float s = 0.f;
#pragma unroll
                for (int y = 0; y < 16; y++) s += s_at[y * 64 + tid];
                g_attc_bf[b * 512 + ec * 64 + tid] = f2bf(s);
            }
        }
        gbar(++ep);

        // ===== P3: gates0 + cell0 (128 blocks x 8 d, full K=2560) =====
        if (bid < 128) {
            unsigned short* xs = (unsigned short*)smem;
            float* red = (float*)(smem + RED_OFF);
            uint4* xd = (uint4*)xs;
            for (int i = tid; i < 5120; i += NTH) {
                int b = i / 320, q = i - b * 320;
                uint4 v;
                if (q < 128)      v = ((const uint4*)g_eys_bf)[(size_t)(b * LL + l) * 128 + q];
                else if (q < 192) v = ((const uint4*)g_attc_bf)[b * 64 + (q - 128)];
                else              v = ((const uint4*)g_z0bf)[b * 128 + (q - 192)];
                xd[b * 321 + q] = v;
            }
            __syncthreads();
            int g = wid & 3, ks = wid >> 2;
            float c[4] = {0.f, 0.f, 0.f, 0.f};
            warp_mma((const uint4*)g_W0F, 80, g * 128 + bid, ks * 20, 20, xs, XS0, lane, c);
            float* rw = &red[(wid * 32 + lane) * 4];
            rw[0] = c[0]; rw[1] = c[1]; rw[2] = c[2]; rw[3] = c[3];
            __syncthreads();
            if (tid < 128) {
                int b = tid >> 3, dl = tid & 7, d = bid * 8 + dl;
                int lr = (b & 7) * 4 + (dl >> 1);
                int rg = ((b >> 3) << 1) + (dl & 1);
                float gv4[4];
#pragma unroll
                for (int gg = 0; gg < 4; gg++) {
                    float s = 0.f;
#pragma unroll
                    for (int k2 = 0; k2 < 4; k2++) s += red[((k2 * 4 + gg) * 32 + lr) * 4 + rg];
                    gv4[gg] = s;
                }
                float gi = gv4[0] + g_b0[d], gf = gv4[1] + g_b0[1024 + d];
                float gg = gv4[2] + g_b0[2048 + d], go = gv4[3] + g_b0[3072 + d];
                int u = b * 1024 + d;
                float cc = sigm(gf) * g_c0[u] + sigm(gi) * tanh_ap(gg);
                float h = sigm(go) * tanh_ap(cc);
                g_c0[u] = cc;
                unsigned short hb = f2bf(h);
                g_z0bf[u] = hb;
                g_x1bf[b * 2048 + d] = hb;
                g_x1bf[b * 2048 + 1024 + d] = g_z1bf[u];
            }
        }
        gbar(++ep);

        // ===== P4: gates1+cell1 (128 blocks) | dec_proj (16 blocks) =====
        if (bid < 128) {
            unsigned short* xs = (unsigned short*)smem;
            float* red = (float*)(smem + RED_OFF);
            uint4* xd = (uint4*)xs;
            for (int i = tid; i < 4096; i += NTH) {
                int b = i >> 8, q = i & 255;
                xd[b * 257 + q] = ((const uint4*)g_x1bf)[b * 256 + q];
            }
            __syncthreads();
            int g = wid & 3, ks = wid >> 2;
            float c[4] = {0.f, 0.f, 0.f, 0.f};
            warp_mma((const uint4*)g_W1F, 64, g * 128 + bid, ks * 16, 16, xs, XS1, lane, c);
            float* rw = &red[(wid * 32 + lane) * 4];
            rw[0] = c[0]; rw[1] = c[1]; rw[2] = c[2]; rw[3] = c[3];
            __syncthreads();
            if (tid < 128) {
                int b = tid >> 3, dl = tid & 7, d = bid * 8 + dl;
                int lr = (b & 7) * 4 + (dl >> 1);
                int rg = ((b >> 3) << 1) + (dl & 1);
                float gv4[4];
#pragma unroll
                for (int gg = 0; gg < 4; gg++) {
                    float s = 0.f;
#pragma unroll
                    for (int k2 = 0; k2 < 4; k2++) s += red[((k2 * 4 + gg) * 32 + lr) * 4 + rg];
                    gv4[gg] = s;
                }
                float gi = gv4[0] + g_b1[d], gf = gv4[1] + g_b1[1024 + d];
                float gg = gv4[2] + g_b1[2048 + d], go = gv4[3] + g_b1[3072 + d];
                int u = b * 1024 + d;
                float cc = sigm(gf) * g_c1[u] + sigm(gi) * tanh_ap(gg);
                float h = sigm(go) * tanh_ap(cc);
                g_c1[u] = cc;
                unsigned short hb = f2bf(h);
                g_z1bf[u] = hb;
                g_zallbf[((size_t)b * LL + l) * 1024 + d] = hb;
            }
        } else if (bid < 144) {
            unsigned short* xs = (unsigned short*)smem;
            float* red = (float*)(smem + RED_OFF);
            uint4* xd = (uint4*)xs;
            for (int i = tid; i < 2048; i += NTH) {
                int b = i >> 7, q = i & 127;
                xd[b * 129 + q] = ((const uint4*)g_z0bf)[b * 128 + q];
            }
            __syncthreads();
            int ti = wid & 3, ks = wid >> 2;
            float c[4] = {0.f, 0.f, 0.f, 0.f};
            warp_mma((const uint4*)g_WdF, 32, (bid - 128) * 4 + ti, ks * 8, 8, xs, XSD, lane, c);
            float* rw = &red[(wid * 32 + lane) * 4];
            rw[0] = c[0]; rw[1] = c[1]; rw[2] = c[2]; rw[3] = c[3];
            __syncthreads();
            {
                int ti2 = tid >> 7, rem = tid & 127;
                int b = rem >> 3, al = rem & 7;
                int lr = (b & 7) * 4 + (al >> 1);
                int rg = ((b >> 3) << 1) + (al & 1);
                float s = 0.f;
#pragma unroll
                for (int k2 = 0; k2 < 4; k2++) s += red[((k2 * 4 + ti2) * 32 + lr) * 4 + rg];
                g_dp[b * 512 + (bid - 128) * 32 + ti2 * 8 + al] = s;
            }
        }
        gbar(++ep);
    }
}

// ---------------- epilogue: online single-pass logsumexp NLL ----------------
__global__ __launch_bounds__(256) void nll_kernel(const int* __restrict__ ys_pad) {
    __shared__ float redm[256], reds[256];
    int m = blockIdx.x, tid = threadIdx.x;
    int b = m / LL, l = m % LL;
    const float* row = &g_logits[(size_t)m * OO];
    float mx = -1e30f, s = 0.f;
    for (int i = tid; i < OO; i += 256) {
        float v = row[i];
        if (v > mx) { s = s * __expf(mx - v) + 1.0f; mx = v; }
        else s += __expf(v - mx);
    }
    redm[tid] = mx; reds[tid] = s;
    __syncthreads();
    for (int st = 128; st; st >>= 1) {
        if (tid < st) {
            float m2 = redm[tid + st], s2 = reds[tid + st];
            float M = fmaxf(redm[tid], m2);
            reds[tid] = reds[tid] * __expf(redm[tid] - M) + s2 * __expf(m2 - M);
            redm[tid] = M;
        }
        __syncthreads();
    }
    if (tid == 0) {
        int tgt = (l < 96) ? ys_pad[b * 96 + l] : SOSEOS;
        g_nll[m] = logf(reds[0]) + redm[0] - row[tgt];
    }
}
__global__ __launch_bounds__(256) void finalize(float* out) {
    __shared__ float red[256];
    int tid = threadIdx.x;
    float acc = 0.f;
    for (int i = tid; i < BB * LL; i += 256) acc += g_nll[i];
    red[tid] = acc; __syncthreads();
    for (int s = 128; s; s >>= 1) { if (tid < s) red[tid] += red[tid + s]; __syncthreads(); }
    if (tid == 0) out[0] = red[0] * (96.0f / (float)(BB * LL));
}

// ---------------- launch ----------------
extern "C" void kernel_launch(void* const* d_in, const int* in_sizes, int n_in,
                              void* d_out, int out_size) {
    const float* hs_pad = (const float*)d_in[0];
    const int*   hlens  = (const int*)d_in[1];
    const int*   ys_pad = (const int*)d_in[2];
    const float* embed  = (const float*)d_in[3];
    const float* W_ih0  = (const float*)d_in[4];
    const float* W_hh0  = (const float*)d_in[5];
    const float* b_ih0  = (const float*)d_in[6];
    const float* b_hh0  = (const float*)d_in[7];
    const float* W_ih1  = (const float*)d_in[8];
    const float* W_hh1  = (const float*)d_in[9];
    const float* b_ih1  = (const float*)d_in[10];
    const float* b_hh1  = (const float*)d_in[11];
    const float* W_enc  = (const float*)d_in[12];
    const float* b_enc  = (const float*)d_in[13];
    const float* W_dec  = (const float*)d_in[14];
    const float* gvec   = (const float*)d_in[15];
    const float* W_out  = (const float*)d_in[16];
    const float* b_out  = (const float*)d_in[17];
    float* out = (float*)d_out;

    unsigned short *d_w0f, *d_w1f, *d_wdf, *d_wef, *d_wof, *d_hsbf, *d_zallbf, *d_pebf;
    cudaGetSymbolAddress((void**)&d_w0f, g_W0F);
    cudaGetSymbolAddress((void**)&d_w1f, g_W1F);
    cudaGetSymbolAddress((void**)&d_wdf, g_WdF);
    cudaGetSymbolAddress((void**)&d_wef, g_WeF);
    cudaGetSymbolAddress((void**)&d_wof, g_WoF);
    cudaGetSymbolAddress((void**)&d_hsbf, g_hs_bf);
    cudaGetSymbolAddress((void**)&d_zallbf, g_zallbf);
    cudaGetSymbolAddress((void**)&d_pebf, g_preenc_bf);
    float* d_logits;
    cudaGetSymbolAddress((void**)&d_logits, g_logits);

    pack_frag<<<(4096 * 2560 + 255) / 256, 256>>>(W_ih0, W_hh0, 1536, 2560, 4096, d_w0f);
    pack_frag<<<(4096 * 2048 + 255) / 256, 256>>>(W_ih1, W_hh1, 1024, 2048, 4096, d_w1f);
    pack_frag<<<(512 * 512 + 255) / 256, 256>>>(W_enc, W_enc, 512, 512, 512, d_wef);
    pack_frag<<<(5000 * 1024 + 255) / 256, 256>>>(W_out, W_out, 1024, 1024, 5000, d_wof);
    prep_all<<<(BB * TT * EE + 255) / 256, 256>>>(hs_pad, W_dec, b_ih0, b_hh0, b_ih1, b_hh1,
                                                  ys_pad, embed, d_wdf);

    // pre_enc = hs_bf @ W_enc^T + b_enc -> bf16   (M=12800, N=512, K=512)
    gemm_mma<2, 1><<<dim3(8, 400), 512, 32 * (512 + 8) * 2>>>(
        d_hsbf, (const uint4*)d_wef, b_enc, nullptr, d_pebf, BB * TT, AA, EE);

    // all 97 recurrent steps in one persistent kernel
    cudaFuncSetAttribute(decoder_loop, cudaFuncAttributeMaxDynamicSharedMemorySize, SMEM_BYTES);
    decoder_loop<<<NBLK, NTH, SMEM_BYTES>>>(hlens, gvec);

    // logits = zall_bf @ W_out^T + b_out -> fp32  (M=1552, N=5000, K=1024)
    gemm_mma<1, 0><<<dim3(40, 97), 512, 16 * (1024 + 8) * 2>>>(
        d_zallbf, (const uint4*)d_wof, b_out, d_logits, nullptr, BB * LL, OO, DD);

    nll_kernel<<<BB * LL, 256>>>(ys_pad);
    finalize<<<1, 256>>>(out);
}

// round 10
// speedup vs baseline: 2.5517x; 1.0106x over previous
#include <cuda_runtime.h>
#include <cuda_bf16.h>
#include <math.h>
#include <stdint.h>

#define BB 16
#define TT 800
#define EE 512
#define DD 1024
#define AA 512
#define OO 5000
#define LL 97
#define SOSEOS 4999
#define NBLK 148
#define NTH 512

// x staging strides (bf16 elems, +8 pad)
#define XS0 2568   // K0=2560
#define XS1 2056   // K1=2048
#define XSD 1032   // Kd=1024
#define RED_OFF 83968
#define SMEM_BYTES 92160

// ---------------- scratch ----------------
__device__ __align__(16) unsigned short g_preenc_bf[BB * TT * AA];
__device__ __align__(16) unsigned short g_hs_bf[BB * TT * EE];
__device__ __align__(16) unsigned short g_W0F[4096 * 2560];   // mma B-fragment layouts
__device__ __align__(16) unsigned short g_W1F[4096 * 2048];
__device__ __align__(16) unsigned short g_WdF[512 * 1024];
__device__ __align__(16) unsigned short g_WeF[512 * 512];
__device__ __align__(16) unsigned short g_WoF[5000 * 1024];
__device__ __align__(16) unsigned short g_eys_bf[BB * LL * DD];
__device__ __align__(16) unsigned short g_z0bf[BB * DD], g_z1bf[BB * DD];
__device__ __align__(16) unsigned short g_attc_bf[BB * AA];
__device__ __align__(16) unsigned short g_x1bf[BB * 2048];
__device__ __align__(16) unsigned short g_zallbf[BB * LL * DD];
__device__ float g_b0[4096], g_b1[4096];
__device__ float g_c0[BB * DD], g_c1[BB * DD];
__device__ float g_dp[BB * AA];
__device__ float g_escore[BB * TT];
__device__ float g_pm2[BB * LL * 40], g_ps2[BB * LL * 40];
__device__ float g_tgt[BB * LL];
__device__ volatile unsigned g_arr[NBLK];
__device__ volatile unsigned g_rel;

// ---------------- helpers ----------------
__device__ __forceinline__ float tanh_ap(float x) {
    float y; asm("tanh.approx.f32 %0, %1;" : "=f"(y) : "f"(x)); return y;
}
__device__ __forceinline__ float sigm(float x) { return 1.0f / (1.0f + __expf(-x)); }
__device__ __forceinline__ unsigned short f2bf(float v) {
    return __bfloat16_as_ushort(__float2bfloat16_rn(v));
}
__device__ __forceinline__ unsigned pk2bf(float a, float b) {
    return (unsigned)f2bf(a) | ((unsigned)f2bf(b) << 16);
}

// device-wide barrier (148 co-resident blocks) — proven version
__device__ __forceinline__ void gbar(unsigned ep) {
    __syncthreads();
    if (threadIdx.x == 0) {
        __threadfence();
        g_arr[blockIdx.x] = ep;
    }
    if (blockIdx.x == 0) {
        if (threadIdx.x < NBLK) {
            while (g_arr[threadIdx.x] < ep) { }
        }
        __syncthreads();
        if (threadIdx.x == 0) { __threadfence(); g_rel = ep; }
    }
    if (threadIdx.x == 0) {
        while (g_rel < ep) { }
        __threadfence();
    }
    __syncthreads();
}

// ---------------- prolog: pack ALL weights into mma B-fragment layouts ----------------
__device__ __forceinline__ void fragstore(unsigned short* dst, int j, int k, int K, float v) {
    int jt = j >> 3, n = j & 7, kt = k >> 4, kk = k & 15;
    int lane = n * 4 + ((kk & 7) >> 1);
    int comp = ((kt & 1) << 1) + (kk >> 3);
    size_t base = ((size_t)jt * (K >> 5) + (kt >> 1)) * 32 + lane;
    dst[base * 8 + comp * 2 + (kk & 1)] = f2bf(v);
}
#define R0 10485760           // W0: 4096*2560
#define R1 (R0 + 8388608)     // W1: 4096*2048
#define R2 (R1 + 524288)      // Wd: 512*1024
#define R3 (R2 + 262144)      // We: 512*512
#define R4 (R3 + 5120000)     // Wo: 5000*1024
__global__ void pack_all(const float* __restrict__ Wih0, const float* __restrict__ Whh0,
                         const float* __restrict__ Wih1, const float* __restrict__ Whh1,
                         const float* __restrict__ Wenc, const float* __restrict__ Wout,
                         const float* __restrict__ Wdec) {
    int i = blockIdx.x * 256 + threadIdx.x;
    if (i < R0) {
        int j = i / 2560, k = i - j * 2560;
        float v = (k < 1536) ? Wih0[(size_t)j * 1536 + k] : Whh0[(size_t)j * 1024 + (k - 1536)];
        fragstore(g_W0F, j, k, 2560, v);
    } else if (i < R1) {
        int q = i - R0;
        int j = q / 2048, k = q - j * 2048;
        float v = (k < 1024) ? Wih1[(size_t)j * 1024 + k] : Whh1[(size_t)j * 1024 + (k - 1024)];
        fragstore(g_W1F, j, k, 2048, v);
    } else if (i < R2) {
        int q = i - R1;
        int j = q >> 10, k = q & 1023;
        fragstore(g_WdF, j, k, 1024, Wdec[(size_t)j * 1024 + k]);
    } else if (i < R3) {
        int q = i - R2;
        int j = q >> 9, k = q & 511;
        fragstore(g_WeF, j, k, 512, Wenc[(size_t)j * 512 + k]);
    } else if (i < R4) {
        int q = i - R3;
        int j = q >> 10, k = q & 1023;
        fragstore(g_WoF, j, k, 1024, Wout[(size_t)j * 1024 + k]);
    }
}

// merged small prolog
__global__ void prep_all(const float* __restrict__ hs,
                         const float* __restrict__ bih0, const float* __restrict__ bhh0,
                         const float* __restrict__ bih1, const float* __restrict__ bhh1,
                         const int* __restrict__ ys_pad, const float* __restrict__ embed) {
    int idx = blockIdx.x * 256 + threadIdx.x;
    if (idx < BB * TT * EE) g_hs_bf[idx] = f2bf(hs[idx]);
    if (idx < 4096) {
        g_b0[idx] = bih0[idx] + bhh0[idx];
        g_b1[idx] = bih1[idx] + bhh1[idx];
    }
    if (idx < BB * DD) {
        g_c0[idx] = 0.f; g_c1[idx] = 0.f;
        g_z0bf[idx] = 0; g_z1bf[idx] = 0;
    }
    if (idx < BB * AA) g_dp[idx] = 0.f;
    if (idx < NBLK) g_arr[idx] = 0u;
    if (idx == 0) g_rel = 0u;
    if (idx < BB * LL * DD) {
        int m = idx >> 10, d = idx & 1023;
        int b = m / LL, l = m % LL;
        int tok = (l == 0) ? SOSEOS : ys_pad[b * 96 + l - 1];
        g_eys_bf[idx] = f2bf(embed[(size_t)tok * DD + d]);
    }
}

// ---------------- warp-level mma over one n8 tile, k-slice ----------------
__device__ __forceinline__ void warp_mma(const uint4* __restrict__ wf, int KT32, int jt,
                                         int ktp0, int nktp, const unsigned short* xs,
                                         int XSTR, int lane, float* c) {
    int m = lane >> 3, r = lane & 7;
    int row = r + ((m & 1) << 3);
    int colh = m >> 1;
    unsigned sbase = (unsigned)__cvta_generic_to_shared(xs) + (unsigned)((row * XSTR + colh * 8) * 2);
    const uint4* wp = wf + (size_t)jt * KT32 * 32 + lane;
#pragma unroll 4
    for (int t = 0; t < nktp; t++) {
        int ktp = ktp0 + t;
        unsigned a0,a1,a2,a3, e0,e1,e2,e3;
        unsigned addr0 = sbase + (unsigned)(ktp * 64);
        asm volatile("ldmatrix.sync.aligned.m8n8.x4.shared.b16 {%0,%1,%2,%3}, [%4];"
            : "=r"(a0),"=r"(a1),"=r"(a2),"=r"(a3) : "r"(addr0));
        asm volatile("ldmatrix.sync.aligned.m8n8.x4.shared.b16 {%0,%1,%2,%3}, [%4];"
            : "=r"(e0),"=r"(e1),"=r"(e2),"=r"(e3) : "r"(addr0 + 32u));
        uint4 wv = wp[(size_t)ktp * 32];
        asm volatile("mma.sync.aligned.m16n8k16.row.col.f32.bf16.bf16.f32 "
            "{%0,%1,%2,%3}, {%4,%5,%6,%7}, {%8,%9}, {%0,%1,%2,%3};"
            : "+f"(c[0]),"+f"(c[1]),"+f"(c[2]),"+f"(c[3])
            : "r"(a0),"r"(a1),"r"(a2),"r"(a3), "r"(wv.x),"r"(wv.y));
        asm volatile("mma.sync.aligned.m16n8k16.row.col.f32.bf16.bf16.f32 "
            "{%0,%1,%2,%3}, {%4,%5,%6,%7}, {%8,%9}, {%0,%1,%2,%3};"
            : "+f"(c[0]),"+f"(c[1]),"+f"(c[2]),"+f"(c[3])
            : "r"(e0),"r"(e1),"r"(e2),"r"(e3), "r"(wv.z),"r"(wv.w));
    }
}

// ---------------- tensor-core GEMM (pre_enc): Cbf[M,N] = A x Bfrag^T + bias ----------------
template <int MSL, int STORE_BF>
__global__ __launch_bounds__(512) void gemm_mma(const unsigned short* __restrict__ A,
        const uint4* __restrict__ BF, const float* __restrict__ bias,
        float* __restrict__ C, unsigned short* __restrict__ Cbf,
        int M, int N, int K) {
    extern __shared__ __align__(16) unsigned short xsd[];
    const int XSTR = K + 8;
    const int tid = threadIdx.x, lane = tid & 31, wid = tid >> 5;
    const int MT = MSL * 16, NTILE = 16 / MSL;
    int m0 = blockIdx.y * MT;
    int n0 = blockIdx.x * NTILE * 8;
    int kq = K >> 3;
    const uint4* Ag = (const uint4*)A;
    for (int i = tid; i < MT * kq; i += 512) {
        int r = i / kq, q = i - r * kq;
        ((uint4*)(xsd + r * XSTR))[q] = Ag[(size_t)(m0 + r) * kq + q];
    }
    __syncthreads();
    int mi = wid / NTILE, nj = wid % NTILE;
    int jt = (n0 >> 3) + nj;
    if (jt * 8 < N) {
        float c[4] = {0.f, 0.f, 0.f, 0.f};
        warp_mma(BF, K >> 5, jt, 0, K >> 5, xsd + mi * 16 * XSTR, XSTR, lane, c);
        int row0 = m0 + mi * 16;
#pragma unroll
        for (int r = 0; r < 4; r++) {
            int row = row0 + (lane >> 2) + 8 * (r >> 1);
            int col = jt * 8 + (lane & 3) * 2 + (r & 1);
            if (col < N) {
                float v = c[r] + bias[col];
                if (STORE_BF) Cbf[(size_t)row * N + col] = f2bf(v);
                else          C[(size_t)row * N + col] = v;
            }
        }
    }
}

// ---------------- fused logits GEMM + partial logsumexp NLL ----------------
// grid (40, 97): by = 16-row slice, bx = 128-col slice. No logits materialization.
__global__ __launch_bounds__(512) void gemm_logits_nll(const unsigned short* __restrict__ A,
        const uint4* __restrict__ BF, const float* __restrict__ bias,
        const int* __restrict__ ys_pad) {
    extern __shared__ __align__(16) unsigned short xsd[];
    const int XSTR = DD + 8;                       // 1032
    float* sl = (float*)(xsd + 16 * XSTR);         // [16][132] fp32
    const int tid = threadIdx.x, lane = tid & 31, wid = tid >> 5;
    int m0 = blockIdx.y * 16, bx = blockIdx.x;
    const uint4* Ag = (const uint4*)A;
    for (int i = tid; i < 16 * 128; i += 512) {
        int r = i >> 7, q = i & 127;
        ((uint4*)(xsd + r * XSTR))[q] = Ag[(size_t)(m0 + r) * 128 + q];
    }
    __syncthreads();
    int jt = bx * 16 + wid;
    float c[4] = {0.f, 0.f, 0.f, 0.f};
    if (jt * 8 < OO)
        warp_mma(BF, 32, jt, 0, 32, xsd, XSTR, lane, c);
#pragma unroll
    for (int r = 0; r < 4; r++) {
        int row = (lane >> 2) + 8 * (r >> 1);
        int coll = wid * 8 + (lane & 3) * 2 + (r & 1);
        int gcol = bx * 128 + coll;
        sl[row * 132 + coll] = (gcol < OO) ? c[r] + bias[gcol] : -1e30f;
    }
    __syncthreads();
    {
        int row = wid;       // 16 warps, one row each
        float v[4];
#pragma unroll
        for (int i = 0; i < 4; i++) v[i] = sl[row * 132 + lane * 4 + i];
        float mx = fmaxf(fmaxf(v[0], v[1]), fmaxf(v[2], v[3]));
#pragma unroll
        for (int o = 16; o; o >>= 1) mx = fmaxf(mx, __shfl_xor_sync(~0u, mx, o));
        float s = __expf(v[0] - mx) + __expf(v[1] - mx) + __expf(v[2] - mx) + __expf(v[3] - mx);
#pragma unroll
        for (int o = 16; o; o >>= 1) s += __shfl_xor_sync(~0u, s, o);
        int grow = m0 + row;
        if (lane == 0) {
            g_pm2[grow * 40 + bx] = mx;
            g_ps2[grow * 40 + bx] = s;
            int b = grow / LL, l = grow % LL;
            int tgt = (l < 96) ? ys_pad[b * 96 + l] : SOSEOS;
            if (tgt >= bx * 128 && tgt < bx * 128 + 128)
                g_tgt[grow] = sl[row * 132 + (tgt - bx * 128)];
        }
    }
}

__global__ __launch_bounds__(512) void finalize_nll(float* out) {
    __shared__ float red[512];
    int tid = threadIdx.x;
    float acc = 0.f;
    for (int row = tid; row < BB * LL; row += 512) {
        float M = -1e30f;
#pragma unroll 8
        for (int j = 0; j < 40; j++) M = fmaxf(M, g_pm2[row * 40 + j]);
        float S = 0.f;
#pragma unroll 8
        for (int j = 0; j < 40; j++) S += g_ps2[row * 40 + j] * __expf(g_pm2[row * 40 + j] - M);
        acc += logf(S) + M - g_tgt[row];
    }
    red[tid] = acc; __syncthreads();
    for (int s = 256; s; s >>= 1) { if (tid < s) red[tid] += red[tid + s]; __syncthreads(); }
    if (tid == 0) out[0] = red[0] * (96.0f / (float)(BB * LL));
}

// ---------------- persistent decoder loop (R6/R9 structure; P1 uses bf16x2 tanh) ----------------
extern "C" __global__ void __launch_bounds__(NTH, 1)
decoder_loop(const int* __restrict__ hlens, const float* __restrict__ gvec) {
    extern __shared__ __align__(16) char smem[];
    __shared__ float s_red[16];
    __shared__ float s_bc[2];
    const int bid = blockIdx.x, tid = threadIdx.x;
    const int lane = tid & 31, wid = tid >> 5;
    unsigned ep = 0;

    for (int l = 0; l < LL; l++) {
        // ===== P1: e[b,t] = sum_a gvec[a]*tanh(pre_enc + dp)  (bf16x2 MUFU path) =====
        {
            int r0 = bid * 86 + min(bid, 72);
            int nr = 86 + (bid < 72 ? 1 : 0);
            int b0 = r0 / 800;
            unsigned* dp2 = (unsigned*)smem;              // 512 packed words (2 b slices x 256)
            float2* gv2 = (float2*)(smem + 2048);         // 256 float2
            if (tid < 512) {
                int s = tid >> 8, q = tid & 255;
                int bb = b0 + s;
                unsigned pk = 0;
                if (bb < 16) pk = pk2bf(g_dp[bb * 512 + 2 * q], g_dp[bb * 512 + 2 * q + 1]);
                dp2[tid] = pk;
                if (tid < 256) gv2[tid] = make_float2(gvec[2 * tid], gvec[2 * tid + 1]);
            }
            __syncthreads();
            for (int r = r0 + wid; r < r0 + nr; r += 16) {
                int b = r / 800;
                const unsigned* pe = (const unsigned*)g_preenc_bf + (size_t)r * 256;
                const unsigned* dpb = dp2 + (b - b0) * 256;
                float acc = 0.f;
#pragma unroll
                for (int p = 0; p < 8; p++) {
                    int q = lane + 32 * p;
                    unsigned v = pe[q];
                    unsigned d = dpb[q];
                    unsigned sm2, t2;
                    asm("add.rn.bf16x2 %0, %1, %2;" : "=r"(sm2) : "r"(v), "r"(d));
                    asm("tanh.approx.bf16x2 %0, %1;" : "=r"(t2) : "r"(sm2));
                    float lo = __uint_as_float(t2 << 16);
                    float hi = __uint_as_float(t2 & 0xffff0000u);
                    float2 g2 = gv2[q];
                    acc = fmaf(g2.x, lo, fmaf(g2.y, hi, acc));
                }
#pragma unroll
                for (int o = 16; o; o >>= 1) acc += __shfl_xor_sync(~0u, acc, o);
                if (lane == 0) g_escore[r] = acc;
            }
        }
        gbar(++ep);

        // ===== P2: softmax + att_c (bf16) =====
        if (bid < 128) {
            int b = bid >> 3, ec = bid & 7;
            int hlen = hlens[b];
            float* s_w  = (float*)smem;            // 800
            float* s_at = (float*)(smem + 4096);   // 1024
            const float* e = &g_escore[b * 800];
            float mx = -1e30f;
            for (int t = tid; t < 800; t += NTH)
                if (t < hlen) mx = fmaxf(mx, e[t]);
#pragma unroll
            for (int o = 16; o; o >>= 1) mx = fmaxf(mx, __shfl_xor_sync(~0u, mx, o));
            if (lane == 0) s_red[wid] = mx;
            __syncthreads();
            if (tid == 0) { float m = s_red[0]; for (int i = 1; i < 16; i++) m = fmaxf(m, s_red[i]); s_bc[0] = m; }
            __syncthreads();
            mx = s_bc[0];
            float sum = 0.f;
            for (int t = tid; t < 800; t += NTH) {
                float w = (t < hlen) ? __expf(2.0f * (e[t] - mx)) : 0.f;
                s_w[t] = w;
                sum += w;
            }
#pragma unroll
            for (int o = 16; o; o >>= 1) sum += __shfl_xor_sync(~0u, sum, o);
            if (lane == 0) s_red[wid] = sum;
            __syncthreads();
            if (tid == 0) { float s = 0.f; for (int i = 0; i < 16; i++) s += s_red[i]; s_bc[1] = 1.0f / s; }
            __syncthreads();
            float inv = s_bc[1];
            for (int t = tid; t < 800; t += NTH) s_w[t] *= inv;
            __syncthreads();
            {
                const unsigned* hp = (const unsigned*)g_hs_bf + (size_t)b * 800 * 256 + ec * 32 + lane;
                float a0 = 0.f, a1 = 0.f;
#pragma unroll 5
                for (int t = wid; t < 800; t += 16) {
                    unsigned v = hp[(size_t)t * 256];
                    float w = s_w[t];
                    a0 = fmaf(w, __uint_as_float(v << 16), a0);
                    a1 = fmaf(w, __uint_as_float(v & 0xffff0000u), a1);
                }
                *(float2*)&s_at[wid * 64 + lane * 2] = make_float2(a0, a1);
            }
            __syncthreads();
            if (tid < 64) {
                float s = 0.f;
#pragma unroll
                for (int y = 0; y < 16; y++) s += s_at[y * 64 + tid];
                g_attc_bf[b * 512 + ec * 64 + tid] = f2bf(s);
            }
        }
        gbar(++ep);

        // ===== P3: gates0 + cell0 (128 blocks x 8 d, full K=2560) =====
        if (bid < 128) {
            unsigned short* xs = (unsigned short*)smem;
            float* red = (float*)(smem + RED_OFF);
            uint4* xd = (uint4*)xs;
            for (int i = tid; i < 5120; i += NTH) {
                int b = i / 320, q = i - b * 320;
                uint4 v;
                if (q < 128)      v = ((const uint4*)g_eys_bf)[(size_t)(b * LL + l) * 128 + q];
                else if (q < 192) v = ((const uint4*)g_attc_bf)[b * 64 + (q - 128)];
                else              v = ((const uint4*)g_z0bf)[b * 128 + (q - 192)];
                xd[b * 321 + q] = v;
            }
            __syncthreads();
            int g = wid & 3, ks = wid >> 2;
            float c[4] = {0.f, 0.f, 0.f, 0.f};
            warp_mma((const uint4*)g_W0F, 80, g * 128 + bid, ks * 20, 20, xs, XS0, lane, c);
            float* rw = &red[(wid * 32 + lane) * 4];
            rw[0] = c[0]; rw[1] = c[1]; rw[2] = c[2]; rw[3] = c[3];
            __syncthreads();
            if (tid < 128) {
                int b = tid >> 3, dl = tid & 7, d = bid * 8 + dl;
                int lr = (b & 7) * 4 + (dl >> 1);
                int rg = ((b >> 3) << 1) + (dl & 1);
                float gv4[4];
#pragma unroll
                for (int gg = 0; gg < 4; gg++) {
                    float s = 0.f;
#pragma unroll
                    for (int k2 = 0; k2 < 4; k2++) s += red[((k2 * 4 + gg) * 32 + lr) * 4 + rg];
                    gv4[gg] = s;
                }
                float gi = gv4[0] + g_b0[d], gf = gv4[1] + g_b0[1024 + d];
                float gg = gv4[2] + g_b0[2048 + d], go = gv4[3] + g_b0[3072 + d];
                int u = b * 1024 + d;
                float cc = sigm(gf) * g_c0[u] + sigm(gi) * tanh_ap(gg);
                float h = sigm(go) * tanh_ap(cc);
                g_c0[u] = cc;
                unsigned short hb = f2bf(h);
                g_z0bf[u] = hb;
                g_x1bf[b * 2048 + d] = hb;
                g_x1bf[b * 2048 + 1024 + d] = g_z1bf[u];
            }
        }
        gbar(++ep);

        // ===== P4: gates1+cell1 (128 blocks) | dec_proj (16 blocks) =====
        if (bid < 128) {
            unsigned short* xs = (unsigned short*)smem;
            float* red = (float*)(smem + RED_OFF);
            uint4* xd = (uint4*)xs;
            for (int i = tid; i < 4096; i += NTH) {
                int b = i >> 8, q = i & 255;
                xd[b * 257 + q] = ((const uint4*)g_x1bf)[b * 256 + q];
            }
            __syncthreads();
            int g = wid & 3, ks = wid >> 2;
            float c[4] = {0.f, 0.f, 0.f, 0.f};
            warp_mma((const uint4*)g_W1F, 64, g * 128 + bid, ks * 16, 16, xs, XS1, lane, c);
            float* rw = &red[(wid * 32 + lane) * 4];
            rw[0] = c[0]; rw[1] = c[1]; rw[2] = c[2]; rw[3] = c[3];
            __syncthreads();
            if (tid < 128) {
                int b = tid >> 3, dl = tid & 7, d = bid * 8 + dl;
                int lr = (b & 7) * 4 + (dl >> 1);
                int rg = ((b >> 3) << 1) + (dl & 1);
                float gv4[4];
#pragma unroll
                for (int gg = 0; gg < 4; gg++) {
                    float s = 0.f;
#pragma unroll
                    for (int k2 = 0; k2 < 4; k2++) s += red[((k2 * 4 + gg) * 32 + lr) * 4 + rg];
                    gv4[gg] = s;
                }
                float gi = gv4[0] + g_b1[d], gf = gv4[1] + g_b1[1024 + d];
                float gg = gv4[2] + g_b1[2048 + d], go = gv4[3] + g_b1[3072 + d];
                int u = b * 1024 + d;
                float cc = sigm(gf) * g_c1[u] + sigm(gi) * tanh_ap(gg);
                float h = sigm(go) * tanh_ap(cc);
                g_c1[u] = cc;
                unsigned short hb = f2bf(h);
                g_z1bf[u] = hb;
                g_zallbf[((size_t)b * LL + l) * 1024 + d] = hb;
            }
        } else if (bid < 144) {
            unsigned short* xs = (unsigned short*)smem;
            float* red = (float*)(smem + RED_OFF);
            uint4* xd = (uint4*)xs;
            for (int i = tid; i < 2048; i += NTH) {
                int b = i >> 7, q = i & 127;
                xd[b * 129 + q] = ((const uint4*)g_z0bf)[b * 128 + q];
            }
            __syncthreads();
            int ti = wid & 3, ks = wid >> 2;
            float c[4] = {0.f, 0.f, 0.f, 0.f};
            warp_mma((const uint4*)g_WdF, 32, (bid - 128) * 4 + ti, ks * 8, 8, xs, XSD, lane, c);
            float* rw = &red[(wid * 32 + lane) * 4];
            rw[0] = c[0]; rw[1] = c[1]; rw[2] = c[2]; rw[3] = c[3];
            __syncthreads();
            {
                int ti2 = tid >> 7, rem = tid & 127;
                int b = rem >> 3, al = rem & 7;
                int lr = (b & 7) * 4 + (al >> 1);
                int rg = ((b >> 3) << 1) + (al & 1);
                float s = 0.f;
#pragma unroll
                for (int k2 = 0; k2 < 4; k2++) s += red[((k2 * 4 + ti2) * 32 + lr) * 4 + rg];
                g_dp[b * 512 + (bid - 128) * 32 + ti2 * 8 + al] = s;
            }
        }
        gbar(++ep);
    }
}

// ---------------- launch ----------------
extern "C" void kernel_launch(void* const* d_in, const int* in_sizes, int n_in,
                              void* d_out, int out_size) {
    const float* hs_pad = (const float*)d_in[0];
    const int*   hlens  = (const int*)d_in[1];
    const int*   ys_pad = (const int*)d_in[2];
    const float* embed  = (const float*)d_in[3];
    const float* W_ih0  = (const float*)d_in[4];
    const float* W_hh0  = (const float*)d_in[5];
    const float* b_ih0  = (const float*)d_in[6];
    const float* b_hh0  = (const float*)d_in[7];
    const float* W_ih1  = (const float*)d_in[8];
    const float* W_hh1  = (const float*)d_in[9];
    const float* b_ih1  = (const float*)d_in[10];
    const float* b_hh1  = (const float*)d_in[11];
    const float* W_enc  = (const float*)d_in[12];
    const float* b_enc  = (const float*)d_in[13];
    const float* W_dec  = (const float*)d_in[14];
    const float* gvec   = (const float*)d_in[15];
    const float* W_out  = (const float*)d_in[16];
    const float* b_out  = (const float*)d_in[17];
    float* out = (float*)d_out;

    unsigned short *d_wef, *d_wof, *d_hsbf, *d_zallbf, *d_pebf;
    cudaGetSymbolAddress((void**)&d_wef, g_WeF);
    cudaGetSymbolAddress((void**)&d_wof, g_WoF);
    cudaGetSymbolAddress((void**)&d_hsbf, g_hs_bf);
    cudaGetSymbolAddress((void**)&d_zallbf, g_zallbf);
    cudaGetSymbolAddress((void**)&d_pebf, g_preenc_bf);

    pack_all<<<(R4 + 255) / 256, 256>>>(W_ih0, W_hh0, W_ih1, W_hh1, W_enc, W_out, W_dec);
    prep_all<<<(BB * TT * EE + 255) / 256, 256>>>(hs_pad, b_ih0, b_hh0, b_ih1, b_hh1,
                                                  ys_pad, embed);

    // pre_enc = hs_bf @ W_enc^T + b_enc -> bf16   (M=12800, N=512, K=512)
    gemm_mma<2, 1><<<dim3(8, 400), 512, 32 * (512 + 8) * 2>>>(
        d_hsbf, (const uint4*)d_wef, b_enc, nullptr, d_pebf, BB * TT, AA, EE);

    // all 97 recurrent steps in one persistent kernel
    cudaFuncSetAttribute(decoder_loop, cudaFuncAttributeMaxDynamicSharedMemorySize, SMEM_BYTES);
    decoder_loop<<<NBLK, NTH, SMEM_BYTES>>>(hlens, gvec);

    // fused logits GEMM + partial logsumexp (no logits materialization)
    gemm_logits_nll<<<dim3(40, 97), 512, 16 * (DD + 8) * 2 + 16 * 132 * 4>>>(
        d_zallbf, (const uint4*)d_wof, b_out, ys_pad);

    finalize_nll<<<1, 512>>>(out);
}

// round 11
// speedup vs baseline: 2.7658x; 1.0839x over previous
#include <cuda_runtime.h>
#include <cuda_bf16.h>
#include <math.h>
#include <stdint.h>

#define BB 16
#define TT 800
#define EE 512
#define DD 1024
#define AA 512
#define OO 5000
#define LL 97
#define SOSEOS 4999
#define NBLK 148
#define NTH 512

// x staging strides (bf16 elems, +8 pad)
#define XS0 2568   // K0=2560
#define XS1 2056   // K1=2048
#define XSD 1032   // Kd=1024
#define RED_OFF 83968
#define SMEM_BYTES 92160

// ---------------- scratch ----------------
__device__ __align__(16) unsigned short g_preenc_bf[BB * TT * AA];
__device__ __align__(16) unsigned short g_hs_bf[BB * TT * EE];
__device__ __align__(16) unsigned short g_W0F[4096 * 2560];   // mma B-fragment layouts
__device__ __align__(16) unsigned short g_W1F[4096 * 2048];
__device__ __align__(16) unsigned short g_WdF[512 * 1024];
__device__ __align__(16) unsigned short g_WeF[512 * 512];
__device__ __align__(16) unsigned short g_WoF[5000 * 1024];
__device__ __align__(16) unsigned short g_eys_bf[BB * LL * DD];
__device__ __align__(16) unsigned short g_z0bf[BB * DD], g_z1bf[BB * DD];
__device__ __align__(16) unsigned short g_x1bf[BB * 2048];
__device__ __align__(16) unsigned short g_zallbf[BB * LL * DD];
__device__ float g_attc_f[BB * AA];       // unnormalized context accumulator (fp32 atomics)
__device__ float g_sw[BB];                // sum of softmax weights
__device__ float g_b0[4096], g_b1[4096];
__device__ float g_c0[BB * DD], g_c1[BB * DD];
__device__ float g_dp[BB * AA];
__device__ float g_pm2[BB * LL * 40], g_ps2[BB * LL * 40];
__device__ float g_tgt[BB * LL];
__device__ volatile unsigned g_arr[NBLK];
__device__ volatile unsigned g_rel;

// ---------------- helpers ----------------
__device__ __forceinline__ float tanh_ap(float x) {
    float y; asm("tanh.approx.f32 %0, %1;" : "=f"(y) : "f"(x)); return y;
}
__device__ __forceinline__ float sigm(float x) { return 1.0f / (1.0f + __expf(-x)); }
__device__ __forceinline__ unsigned short f2bf(float v) {
    return __bfloat16_as_ushort(__float2bfloat16_rn(v));
}
__device__ __forceinline__ unsigned pk2bf(float a, float b) {
    return (unsigned)f2bf(a) | ((unsigned)f2bf(b) << 16);
}

// device-wide barrier (148 co-resident blocks) — proven version
__device__ __forceinline__ void gbar(unsigned ep) {
    __syncthreads();
    if (threadIdx.x == 0) {
        __threadfence();
        g_arr[blockIdx.x] = ep;
    }
    if (blockIdx.x == 0) {
        if (threadIdx.x < NBLK) {
            while (g_arr[threadIdx.x] < ep) { }
        }
        __syncthreads();
        if (threadIdx.x == 0) { __threadfence(); g_rel = ep; }
    }
    if (threadIdx.x == 0) {
        while (g_rel < ep) { }
        __threadfence();
    }
    __syncthreads();
}

// ---------------- prolog: pack ALL weights into mma B-fragment layouts ----------------
__device__ __forceinline__ void fragstore(unsigned short* dst, int j, int k, int K, float v) {
    int jt = j >> 3, n = j & 7, kt = k >> 4, kk = k & 15;
    int lane = n * 4 + ((kk & 7) >> 1);
    int comp = ((kt & 1) << 1) + (kk >> 3);
    size_t base = ((size_t)jt * (K >> 5) + (kt >> 1)) * 32 + lane;
    dst[base * 8 + comp * 2 + (kk & 1)] = f2bf(v);
}
#define R0 10485760           // W0: 4096*2560
#define R1 (R0 + 8388608)     // W1: 4096*2048
#define R2 (R1 + 524288)      // Wd: 512*1024
#define R3 (R2 + 262144)      // We: 512*512
#define R4 (R3 + 5120000)     // Wo: 5000*1024
__global__ void pack_all(const float* __restrict__ Wih0, const float* __restrict__ Whh0,
                         const float* __restrict__ Wih1, const float* __restrict__ Whh1,
                         const float* __restrict__ Wenc, const float* __restrict__ Wout,
                         const float* __restrict__ Wdec) {
    int i = blockIdx.x * 256 + threadIdx.x;
    if (i < R0) {
        int j = i / 2560, k = i - j * 2560;
        float v = (k < 1536) ? Wih0[(size_t)j * 1536 + k] : Whh0[(size_t)j * 1024 + (k - 1536)];
        fragstore(g_W0F, j, k, 2560, v);
    } else if (i < R1) {
        int q = i - R0;
        int j = q / 2048, k = q - j * 2048;
        float v = (k < 1024) ? Wih1[(size_t)j * 1024 + k] : Whh1[(size_t)j * 1024 + (k - 1024)];
        fragstore(g_W1F, j, k, 2048, v);
    } else if (i < R2) {
        int q = i - R1;
        int j = q >> 10, k = q & 1023;
        fragstore(g_WdF, j, k, 1024, Wdec[(size_t)j * 1024 + k]);
    } else if (i < R3) {
        int q = i - R2;
        int j = q >> 9, k = q & 511;
        fragstore(g_WeF, j, k, 512, Wenc[(size_t)j * 512 + k]);
    } else if (i < R4) {
        int q = i - R3;
        int j = q >> 10, k = q & 1023;
        fragstore(g_WoF, j, k, 1024, Wout[(size_t)j * 1024 + k]);
    }
}

// merged small prolog
__global__ void prep_all(const float* __restrict__ hs,
                         const float* __restrict__ bih0, const float* __restrict__ bhh0,
                         const float* __restrict__ bih1, const float* __restrict__ bhh1,
                         const int* __restrict__ ys_pad, const float* __restrict__ embed) {
    int idx = blockIdx.x * 256 + threadIdx.x;
    if (idx < BB * TT * EE) g_hs_bf[idx] = f2bf(hs[idx]);
    if (idx < 4096) {
        g_b0[idx] = bih0[idx] + bhh0[idx];
        g_b1[idx] = bih1[idx] + bhh1[idx];
    }
    if (idx < BB * DD) {
        g_c0[idx] = 0.f; g_c1[idx] = 0.f;
        g_z0bf[idx] = 0; g_z1bf[idx] = 0;
    }
    if (idx < BB * AA) { g_dp[idx] = 0.f; g_attc_f[idx] = 0.f; }
    if (idx < BB) g_sw[idx] = 0.f;
    if (idx < NBLK) g_arr[idx] = 0u;
    if (idx == 0) g_rel = 0u;
    if (idx < BB * LL * DD) {
        int m = idx >> 10, d = idx & 1023;
        int b = m / LL, l = m % LL;
        int tok = (l == 0) ? SOSEOS : ys_pad[b * 96 + l - 1];
        g_eys_bf[idx] = f2bf(embed[(size_t)tok * DD + d]);
    }
}

// ---------------- warp-level mma over one n8 tile, k-slice ----------------
__device__ __forceinline__ void warp_mma(const uint4* __restrict__ wf, int KT32, int jt,
                                         int ktp0, int nktp, const unsigned short* xs,
                                         int XSTR, int lane, float* c) {
    int m = lane >> 3, r = lane & 7;
    int row = r + ((m & 1) << 3);
    int colh = m >> 1;
    unsigned sbase = (unsigned)__cvta_generic_to_shared(xs) + (unsigned)((row * XSTR + colh * 8) * 2);
    const uint4* wp = wf + (size_t)jt * KT32 * 32 + lane;
#pragma unroll 4
    for (int t = 0; t < nktp; t++) {
        int ktp = ktp0 + t;
        unsigned a0,a1,a2,a3, e0,e1,e2,e3;
        unsigned addr0 = sbase + (unsigned)(ktp * 64);
        asm volatile("ldmatrix.sync.aligned.m8n8.x4.shared.b16 {%0,%1,%2,%3}, [%4];"
            : "=r"(a0),"=r"(a1),"=r"(a2),"=r"(a3) : "r"(addr0));
        asm volatile("ldmatrix.sync.aligned.m8n8.x4.shared.b16 {%0,%1,%2,%3}, [%4];"
            : "=r"(e0),"=r"(e1),"=r"(e2),"=r"(e3) : "r"(addr0 + 32u));
        uint4 wv = wp[(size_t)ktp * 32];
        asm volatile("mma.sync.aligned.m16n8k16.row.col.f32.bf16.bf16.f32 "
            "{%0,%1,%2,%3}, {%4,%5,%6,%7}, {%8,%9}, {%0,%1,%2,%3};"
            : "+f"(c[0]),"+f"(c[1]),"+f"(c[2]),"+f"(c[3])
            : "r"(a0),"r"(a1),"r"(a2),"r"(a3), "r"(wv.x),"r"(wv.y));
        asm volatile("mma.sync.aligned.m16n8k16.row.col.f32.bf16.bf16.f32 "
            "{%0,%1,%2,%3}, {%4,%5,%6,%7}, {%8,%9}, {%0,%1,%2,%3};"
            : "+f"(c[0]),"+f"(c[1]),"+f"(c[2]),"+f"(c[3])
            : "r"(e0),"r"(e1),"r"(e2),"r"(e3), "r"(wv.z),"r"(wv.w));
    }
}

// ---------------- tensor-core GEMM (pre_enc): Cbf[M,N] = A x Bfrag^T + bias ----------------
template <int MSL, int STORE_BF>
__global__ __launch_bounds__(512) void gemm_mma(const unsigned short* __restrict__ A,
        const uint4* __restrict__ BF, const float* __restrict__ bias,
        float* __restrict__ C, unsigned short* __restrict__ Cbf,
        int M, int N, int K) {
    extern __shared__ __align__(16) unsigned short xsd[];
    const int XSTR = K + 8;
    const int tid = threadIdx.x, lane = tid & 31, wid = tid >> 5;
    const int MT = MSL * 16, NTILE = 16 / MSL;
    int m0 = blockIdx.y * MT;
    int n0 = blockIdx.x * NTILE * 8;
    int kq = K >> 3;
    const uint4* Ag = (const uint4*)A;
    for (int i = tid; i < MT * kq; i += 512) {
        int r = i / kq, q = i - r * kq;
        ((uint4*)(xsd + r * XSTR))[q] = Ag[(size_t)(m0 + r) * kq + q];
    }
    __syncthreads();
    int mi = wid / NTILE, nj = wid % NTILE;
    int jt = (n0 >> 3) + nj;
    if (jt * 8 < N) {
        float c[4] = {0.f, 0.f, 0.f, 0.f};
        warp_mma(BF, K >> 5, jt, 0, K >> 5, xsd + mi * 16 * XSTR, XSTR, lane, c);
        int row0 = m0 + mi * 16;
#pragma unroll
        for (int r = 0; r < 4; r++) {
            int row = row0 + (lane >> 2) + 8 * (r >> 1);
            int col = jt * 8 + (lane & 3) * 2 + (r & 1);
            if (col < N) {
                float v = c[r] + bias[col];
                if (STORE_BF) Cbf[(size_t)row * N + col] = f2bf(v);
                else          C[(size_t)row * N + col] = v;
            }
        }
    }
}

// ---------------- fused logits GEMM + partial logsumexp NLL ----------------
__global__ __launch_bounds__(512) void gemm_logits_nll(const unsigned short* __restrict__ A,
        const uint4* __restrict__ BF, const float* __restrict__ bias,
        const int* __restrict__ ys_pad) {
    extern __shared__ __align__(16) unsigned short xsd[];
    const int XSTR = DD + 8;                       // 1032
    float* sl = (float*)(xsd + 16 * XSTR);         // [16][132] fp32
    const int tid = threadIdx.x, lane = tid & 31, wid = tid >> 5;
    int m0 = blockIdx.y * 16, bx = blockIdx.x;
    const uint4* Ag = (const uint4*)A;
    for (int i = tid; i < 16 * 128; i += 512) {
        int r = i >> 7, q = i & 127;
        ((uint4*)(xsd + r * XSTR))[q] = Ag[(size_t)(m0 + r) * 128 + q];
    }
    __syncthreads();
    int jt = bx * 16 + wid;
    float c[4] = {0.f, 0.f, 0.f, 0.f};
    if (jt * 8 < OO)
        warp_mma(BF, 32, jt, 0, 32, xsd, XSTR, lane, c);
#pragma unroll
    for (int r = 0; r < 4; r++) {
        int row = (lane >> 2) + 8 * (r >> 1);
        int coll = wid * 8 + (lane & 3) * 2 + (r & 1);
        int gcol = bx * 128 + coll;
        sl[row * 132 + coll] = (gcol < OO) ? c[r] + bias[gcol] : -1e30f;
    }
    __syncthreads();
    {
        int row = wid;       // 16 warps, one row each
        float v[4];
#pragma unroll
        for (int i = 0; i < 4; i++) v[i] = sl[row * 132 + lane * 4 + i];
        float mx = fmaxf(fmaxf(v[0], v[1]), fmaxf(v[2], v[3]));
#pragma unroll
        for (int o = 16; o; o >>= 1) mx = fmaxf(mx, __shfl_xor_sync(~0u, mx, o));
        float s = __expf(v[0] - mx) + __expf(v[1] - mx) + __expf(v[2] - mx) + __expf(v[3] - mx);
#pragma unroll
        for (int o = 16; o; o >>= 1) s += __shfl_xor_sync(~0u, s, o);
        int grow = m0 + row;
        if (lane == 0) {
            g_pm2[grow * 40 + bx] = mx;
            g_ps2[grow * 40 + bx] = s;
            int b = grow / LL, l = grow % LL;
            int tgt = (l < 96) ? ys_pad[b * 96 + l] : SOSEOS;
            if (tgt >= bx * 128 && tgt < bx * 128 + 128)
                g_tgt[grow] = sl[row * 132 + (tgt - bx * 128)];
        }
    }
}

__global__ __launch_bounds__(512) void finalize_nll(float* out) {
    __shared__ float red[512];
    int tid = threadIdx.x;
    float acc = 0.f;
    for (int row = tid; row < BB * LL; row += 512) {
        float M = -1e30f;
#pragma unroll 8
        for (int j = 0; j < 40; j++) M = fmaxf(M, g_pm2[row * 40 + j]);
        float S = 0.f;
#pragma unroll 8
        for (int j = 0; j < 40; j++) S += g_ps2[row * 40 + j] * __expf(g_pm2[row * 40 + j] - M);
        acc += logf(S) + M - g_tgt[row];
    }
    red[tid] = acc; __syncthreads();
    for (int s = 256; s; s >>= 1) { if (tid < s) red[tid] += red[tid + s]; __syncthreads(); }
    if (tid == 0) out[0] = red[0] * (96.0f / (float)(BB * LL));
}

// ---------------- persistent decoder loop: 3 phases/step ----------------
extern "C" __global__ void __launch_bounds__(NTH, 1)
decoder_loop(const int* __restrict__ hlens, const float* __restrict__ gvec) {
    extern __shared__ __align__(16) char smem[];
    const int bid = blockIdx.x, tid = threadIdx.x;
    const int lane = tid & 31, wid = tid >> 5;
    unsigned ep = 0;

    for (int l = 0; l < LL; l++) {
        // ===== P1: scores + exp (no-max) + unnormalized partial context, all fused =====
        {
            int r0 = bid * 86 + min(bid, 72);
            int nr = 86 + (bid < 72 ? 1 : 0);
            int b0 = r0 / 800;
            bool spans2 = ((r0 + nr - 1) / 800) > b0;
            int hl0 = hlens[b0];
            int hl1 = (b0 + 1 < 16) ? hlens[b0 + 1] : 0;
            unsigned* dp2 = (unsigned*)smem;                  // [2][256] packed bf16x2
            float2* gv2 = (float2*)(smem + 2048);             // [256]
            float* ctxs = (float*)(smem + 4096);              // [2][16][512] fp32
            float* swarr = (float*)(smem + 4096 + 65536);     // [2][16]
            if (tid < 512) {
                int s = tid >> 8, q = tid & 255;
                int bb = b0 + s;
                unsigned pk = 0;
                if (bb < 16) pk = pk2bf(g_dp[bb * 512 + 2 * q], g_dp[bb * 512 + 2 * q + 1]);
                dp2[tid] = pk;
                if (tid < 256) gv2[tid] = make_float2(gvec[2 * tid], gvec[2 * tid + 1]);
            }
            __syncthreads();
            float accA[16], accB[16];
#pragma unroll
            for (int i = 0; i < 16; i++) { accA[i] = 0.f; accB[i] = 0.f; }
            float swA = 0.f, swB = 0.f;
            const unsigned* hsb = (const unsigned*)g_hs_bf;
            for (int r = r0 + wid; r < r0 + nr; r += 16) {
                int b = (r >= (b0 + 1) * 800) ? (b0 + 1) : b0;
                int t = r - b * 800;
                const unsigned* pe = (const unsigned*)g_preenc_bf + (size_t)r * 256;
                const unsigned* dpb = dp2 + (b - b0) * 256;
                float acc = 0.f;
#pragma unroll
                for (int p = 0; p < 8; p++) {
                    int q = lane + 32 * p;
                    unsigned v = pe[q];
                    unsigned d = dpb[q];
                    unsigned sm2, t2;
                    asm("add.rn.bf16x2 %0, %1, %2;" : "=r"(sm2) : "r"(v), "r"(d));
                    asm("tanh.approx.bf16x2 %0, %1;" : "=r"(t2) : "r"(sm2));
                    float lo = __uint_as_float(t2 << 16);
                    float hi = __uint_as_float(t2 & 0xffff0000u);
                    float2 g2 = gv2[q];
                    acc = fmaf(g2.x, lo, fmaf(g2.y, hi, acc));
                }
#pragma unroll
                for (int o = 16; o; o >>= 1) acc += __shfl_xor_sync(~0u, acc, o);
                int hl = (b == b0) ? hl0 : hl1;
                float w = (t < hl) ? __expf(2.0f * acc) : 0.f;
                const unsigned* hp = hsb + (size_t)r * 256;
                if (b == b0) {
                    if (lane == 0) swA += w;
#pragma unroll
                    for (int p = 0; p < 8; p++) {
                        unsigned v = hp[p * 32 + lane];
                        accA[2 * p]     = fmaf(w, __uint_as_float(v << 16), accA[2 * p]);
                        accA[2 * p + 1] = fmaf(w, __uint_as_float(v & 0xffff0000u), accA[2 * p + 1]);
                    }
                } else {
                    if (lane == 0) swB += w;
#pragma unroll
                    for (int p = 0; p < 8; p++) {
                        unsigned v = hp[p * 32 + lane];
                        accB[2 * p]     = fmaf(w, __uint_as_float(v << 16), accB[2 * p]);
                        accB[2 * p + 1] = fmaf(w, __uint_as_float(v & 0xffff0000u), accB[2 * p + 1]);
                    }
                }
            }
#pragma unroll
            for (int i = 0; i < 16; i++) {
                ctxs[wid * 512 + i * 32 + lane] = accA[i];
                ctxs[8192 + wid * 512 + i * 32 + lane] = accB[i];
            }
            if (lane == 0) { swarr[wid] = swA; swarr[16 + wid] = swB; }
            __syncthreads();
            // block reduce + global atomic accumulate
            {
                int col = tid;   // 512 columns
                float s0 = 0.f;
#pragma unroll
                for (int y = 0; y < 16; y++) s0 += ctxs[y * 512 + col];
                atomicAdd(&g_attc_f[b0 * 512 + col], s0);
                if (spans2) {
                    float s1 = 0.f;
#pragma unroll
                    for (int y = 0; y < 16; y++) s1 += ctxs[8192 + y * 512 + col];
                    atomicAdd(&g_attc_f[(b0 + 1) * 512 + col], s1);
                }
            }
            if (tid == 0) {
                float s = 0.f;
#pragma unroll
                for (int y = 0; y < 16; y++) s += swarr[y];
                atomicAdd(&g_sw[b0], s);
            }
            if (tid == 32 && spans2) {
                float s = 0.f;
#pragma unroll
                for (int y = 0; y < 16; y++) s += swarr[16 + y];
                atomicAdd(&g_sw[b0 + 1], s);
            }
        }
        gbar(++ep);

        // ===== P2: gates0 + cell0 (128 blocks x 8 d, full K=2560); ctx normalize in staging =====
        if (bid < 128) {
            unsigned short* xs = (unsigned short*)smem;
            float* red = (float*)(smem + RED_OFF);
            uint4* xd = (uint4*)xs;
            for (int i = tid; i < 5120; i += NTH) {
                int b = i / 320, q = i - b * 320;
                uint4 v;
                if (q < 128) {
                    v = ((const uint4*)g_eys_bf)[(size_t)(b * LL + l) * 128 + q];
                } else if (q < 192) {
                    int o = (q - 128) * 8;
                    float4 f0 = *(const float4*)&g_attc_f[b * 512 + o];
                    float4 f1 = *(const float4*)&g_attc_f[b * 512 + o + 4];
                    float inv = __fdividef(1.0f, g_sw[b]);
                    v.x = pk2bf(f0.x * inv, f0.y * inv);
                    v.y = pk2bf(f0.z * inv, f0.w * inv);
                    v.z = pk2bf(f1.x * inv, f1.y * inv);
                    v.w = pk2bf(f1.z * inv, f1.w * inv);
                } else {
                    v = ((const uint4*)g_z0bf)[b * 128 + (q - 192)];
                }
                xd[b * 321 + q] = v;
            }
            __syncthreads();
            int g = wid & 3, ks = wid >> 2;
            float c[4] = {0.f, 0.f, 0.f, 0.f};
            warp_mma((const uint4*)g_W0F, 80, g * 128 + bid, ks * 20, 20, xs, XS0, lane, c);
            float* rw = &red[(wid * 32 + lane) * 4];
            rw[0] = c[0]; rw[1] = c[1]; rw[2] = c[2]; rw[3] = c[3];
            __syncthreads();
            if (tid < 128) {
                int b = tid >> 3, dl = tid & 7, d = bid * 8 + dl;
                int lr = (b & 7) * 4 + (dl >> 1);
                int rg = ((b >> 3) << 1) + (dl & 1);
                float gv4[4];
#pragma unroll
                for (int gg = 0; gg < 4; gg++) {
                    float s = 0.f;
#pragma unroll
                    for (int k2 = 0; k2 < 4; k2++) s += red[((k2 * 4 + gg) * 32 + lr) * 4 + rg];
                    gv4[gg] = s;
                }
                float gi = gv4[0] + g_b0[d], gf = gv4[1] + g_b0[1024 + d];
                float gg = gv4[2] + g_b0[2048 + d], go = gv4[3] + g_b0[3072 + d];
                int u = b * 1024 + d;
                float cc = sigm(gf) * g_c0[u] + sigm(gi) * tanh_ap(gg);
                float h = sigm(go) * tanh_ap(cc);
                g_c0[u] = cc;
                unsigned short hb = f2bf(h);
                g_z0bf[u] = hb;
                g_x1bf[b * 2048 + d] = hb;
                g_x1bf[b * 2048 + 1024 + d] = g_z1bf[u];
            }
        }
        gbar(++ep);

        // ===== P3: gates1+cell1 (128) | dec_proj (16) | zero ctx accumulators (4) =====
        if (bid < 128) {
            unsigned short* xs = (unsigned short*)smem;
            float* red = (float*)(smem + RED_OFF);
            uint4* xd = (uint4*)xs;
            for (int i = tid; i < 4096; i += NTH) {
                int b = i >> 8, q = i & 255;
                xd[b * 257 + q] = ((const uint4*)g_x1bf)[b * 256 + q];
            }
            __syncthreads();
            int g = wid & 3, ks = wid >> 2;
            float c[4] = {0.f, 0.f, 0.f, 0.f};
            warp_mma((const uint4*)g_W1F, 64, g * 128 + bid, ks * 16, 16, xs, XS1, lane, c);
            float* rw = &red[(wid * 32 + lane) * 4];
            rw[0] = c[0]; rw[1] = c[1]; rw[2] = c[2]; rw[3] = c[3];
            __syncthreads();
            if (tid < 128) {
                int b = tid >> 3, dl = tid & 7, d = bid * 8 + dl;
                int lr = (b & 7) * 4 + (dl >> 1);
                int rg = ((b >> 3) << 1) + (dl & 1);
                float gv4[4];
#pragma unroll
                for (int gg = 0; gg < 4; gg++) {
                    float s = 0.f;
#pragma unroll
                    for (int k2 = 0; k2 < 4; k2++) s += red[((k2 * 4 + gg) * 32 + lr) * 4 + rg];
                    gv4[gg] = s;
                }
                float gi = gv4[0] + g_b1[d], gf = gv4[1] + g_b1[1024 + d];
                float gg = gv4[2] + g_b1[2048 + d], go = gv4[3] + g_b1[3072 + d];
                int u = b * 1024 + d;
                float cc = sigm(gf) * g_c1[u] + sigm(gi) * tanh_ap(gg);
                float h = sigm(go) * tanh_ap(cc);
                g_c1[u] = cc;
                unsigned short hb = f2bf(h);
                g_z1bf[u] = hb;
                g_zallbf[((size_t)b * LL + l) * 1024 + d] = hb;
            }
        } else if (bid < 144) {
            unsigned short* xs = (unsigned short*)smem;
            float* red = (float*)(smem + RED_OFF);
            uint4* xd = (uint4*)xs;
            for (int i = tid; i < 2048; i += NTH) {
                int b = i >> 7, q = i & 127;
                xd[b * 129 + q] = ((const uint4*)g_z0bf)[b * 128 + q];
            }
            __syncthreads();
            int ti = wid & 3, ks = wid >> 2;
            float c[4] = {0.f, 0.f, 0.f, 0.f};
            warp_mma((const uint4*)g_WdF, 32, (bid - 128) * 4 + ti, ks * 8, 8, xs, XSD, lane, c);
            float* rw = &red[(wid * 32 + lane) * 4];
            rw[0] = c[0]; rw[1] = c[1]; rw[2] = c[2]; rw[3] = c[3];
            __syncthreads();
            {
                int ti2 = tid >> 7, rem = tid & 127;
                int b = rem >> 3, al = rem & 7;
                int lr = (b & 7) * 4 + (al >> 1);
                int rg = ((b >> 3) << 1) + (al & 1);
                float s = 0.f;
#pragma unroll
                for (int k2 = 0; k2 < 4; k2++) s += red[((k2 * 4 + ti2) * 32 + lr) * 4 + rg];
                g_dp[b * 512 + (bid - 128) * 32 + ti2 * 8 + al] = s;
            }
        } else {
            // blocks 144-147: zero ctx accumulators for the NEXT step
            int base = (bid - 144) * 2048;
            for (int i = tid; i < 2048; i += NTH) g_attc_f[base + i] = 0.f;
            if (bid == 144 && tid < 16) g_sw[tid] = 0.f;
        }
        gbar(++ep);
    }
}

// ---------------- launch ----------------
extern "C" void kernel_launch(void* const* d_in, const int* in_sizes, int n_in,
                              void* d_out, int out_size) {
    const float* hs_pad = (const float*)d_in[0];
    const int*   hlens  = (const int*)d_in[1];
    const int*   ys_pad = (const int*)d_in[2];
    const float* embed  = (const float*)d_in[3];
    const float* W_ih0  = (const float*)d_in[4];
    const float* W_hh0  = (const float*)d_in[5];
    const float* b_ih0  = (const float*)d_in[6];
    const float* b_hh0  = (const float*)d_in[7];
    const float* W_ih1  = (const float*)d_in[8];
    const float* W_hh1  = (const float*)d_in[9];
    const float* b_ih1  = (const float*)d_in[10];
    const float* b_hh1  = (const float*)d_in[11];
    const float* W_enc  = (const float*)d_in[12];
    const float* b_enc  = (const float*)d_in[13];
    const float* W_dec  = (const float*)d_in[14];
    const float* gvec   = (const float*)d_in[15];
    const float* W_out  = (const float*)d_in[16];
    const float* b_out  = (const float*)d_in[17];
    float* out = (float*)d_out;

    unsigned short *d_wef, *d_wof, *d_hsbf, *d_zallbf, *d_pebf;
    cudaGetSymbolAddress((void**)&d_wef, g_WeF);
    cudaGetSymbolAddress((void**)&d_wof, g_WoF);
    cudaGetSymbolAddress((void**)&d_hsbf, g_hs_bf);
    cudaGetSymbolAddress((void**)&d_zallbf, g_zallbf);
    cudaGetSymbolAddress((void**)&d_pebf, g_preenc_bf);

    pack_all<<<(R4 + 255) / 256, 256>>>(W_ih0, W_hh0, W_ih1, W_hh1, W_enc, W_out, W_dec);
    prep_all<<<(BB * TT * EE + 255) / 256, 256>>>(hs_pad, b_ih0, b_hh0, b_ih1, b_hh1,
                                                  ys_pad, embed);

    // pre_enc = hs_bf @ W_enc^T + b_enc -> bf16   (M=12800, N=512, K=512)
    gemm_mma<2, 1><<<dim3(8, 400), 512, 32 * (512 + 8) * 2>>>(
        d_hsbf, (const uint4*)d_wef, b_enc, nullptr, d_pebf, BB * TT, AA, EE);

    // all 97 recurrent steps in one persistent kernel (3 barriers/step)
    cudaFuncSetAttribute(decoder_loop, cudaFuncAttributeMaxDynamicSharedMemorySize, SMEM_BYTES);
    decoder_loop<<<NBLK, NTH, SMEM_BYTES>>>(hlens, gvec);

    // fused logits GEMM + partial logsumexp (no logits materialization)
    gemm_logits_nll<<<dim3(40, 97), 512, 16 * (DD + 8) * 2 + 16 * 132 * 4>>>(
        d_zallbf, (const uint4*)d_wof, b_out, ys_pad);

    finalize_nll<<<1, 512>>>(out);
}